// round 13
// baseline (speedup 1.0000x reference)
#include <cuda_runtime.h>
#include <cuda_bf16.h>
#include <cuda_fp16.h>
#include <cstdint>
#include <math.h>

#define T_STEPS 256
#define B_SZ 64
#define H_SZ 1024
#define H4 4096
#define O_SZ 10000
#define V_SZ 10000
#define TB (T_STEPS * B_SZ)
#define BH (B_SZ * H_SZ)

// ===================== low-level helpers (sm_80+ features only) =============
__device__ __forceinline__ uint32_t smem_u32(const void* p) {
    uint32_t a;
    asm("{ .reg .u64 t; cvta.to.shared.u64 t, %1; cvt.u32.u64 %0, t; }"
        : "=r"(a) : "l"(p));
    return a;
}
__device__ __forceinline__ void ldsm4(uint32_t* r, uint32_t a) {
    asm volatile("ldmatrix.sync.aligned.m8n8.x4.shared.b16 {%0,%1,%2,%3}, [%4];"
                 : "=r"(r[0]), "=r"(r[1]), "=r"(r[2]), "=r"(r[3]) : "r"(a));
}
__device__ __forceinline__ void mma_bf16(float* c, const uint32_t* a,
                                         uint32_t b0, uint32_t b1) {
    asm volatile(
        "mma.sync.aligned.m16n8k16.row.col.f32.bf16.bf16.f32 "
        "{%0,%1,%2,%3}, {%4,%5,%6,%7}, {%8,%9}, {%0,%1,%2,%3};"
        : "+f"(c[0]), "+f"(c[1]), "+f"(c[2]), "+f"(c[3])
        : "r"(a[0]), "r"(a[1]), "r"(a[2]), "r"(a[3]), "r"(b0), "r"(b1));
}
__device__ __forceinline__ void mma_f16(float* c, const uint32_t* a,
                                        uint32_t b0, uint32_t b1) {
    asm volatile(
        "mma.sync.aligned.m16n8k16.row.col.f32.f16.f16.f32 "
        "{%0,%1,%2,%3}, {%4,%5,%6,%7}, {%8,%9}, {%0,%1,%2,%3};"
        : "+f"(c[0]), "+f"(c[1]), "+f"(c[2]), "+f"(c[3])
        : "r"(a[0]), "r"(a[1]), "r"(a[2]), "r"(a[3]), "r"(b0), "r"(b1));
}
__device__ __forceinline__ void cp16(uint32_t dst, const void* src, uint32_t sz) {
    asm volatile("cp.async.cg.shared.global [%0], [%1], 16, %2;"
                 :: "r"(dst), "l"(src), "r"(sz) : "memory");
}
#define CP_COMMIT() asm volatile("cp.async.commit_group;" ::: "memory")
#define CP_WAIT0()  asm volatile("cp.async.wait_group 0;" ::: "memory")
#define CP_WAIT1()  asm volatile("cp.async.wait_group 1;" ::: "memory")
#define CP_WAIT2()  asm volatile("cp.async.wait_group 2;" ::: "memory")
#define BAR_SYNC(id, n) asm volatile("bar.sync %0, %1;" :: "r"(id), "r"(n) : "memory")

__device__ __forceinline__ void split_bf(float x, __nv_bfloat16& hi, __nv_bfloat16& lo) {
    hi = __float2bfloat16(x);
    lo = __float2bfloat16(x - __bfloat162float(hi));
}

// ===================== scratch (device globals) ==============================
#define SCAN_CTAS 128
__device__ float          g_px[(size_t)TB * H4];   // holds pxv[V(+pad), 4H]
__device__ float          g_bc[H4];
__device__ unsigned int   g_flags[SCAN_CTAS];      // per-CTA step flags (barrier)
__device__ __half         g_res16h[(size_t)(T_STEPS + 1) * BH];
__device__ __half         g_emb16h[(size_t)O_SZ * H_SZ];
__device__ __nv_bfloat16  g_WxT_hi[(size_t)H4 * H_SZ],   g_WxT_lo[(size_t)H4 * H_SZ];
__device__ __half         g_WhT16[(size_t)H4 * H_SZ];
__device__ __half         g_WoT16[(size_t)O_SZ * H_SZ];
__device__ __nv_bfloat16  g_Wp_hi[(size_t)H_SZ * H_SZ],  g_Wp_lo[(size_t)H_SZ * H_SZ];
__device__ __half         g_WcT16[(size_t)H4 * H_SZ];

// ===================== pre-pass kernels ======================================
__global__ void split_kernel(const float* __restrict__ in,
                             __nv_bfloat16* __restrict__ hi,
                             __nv_bfloat16* __restrict__ lo, long n) {
    long i = (long)blockIdx.x * blockDim.x + threadIdx.x;
    long stride = (long)gridDim.x * blockDim.x;
    for (; i < n; i += stride) split_bf(in[i], hi[i], lo[i]);
}
__global__ void conv16_kernel(const float* __restrict__ in,
                              __half* __restrict__ o, long n) {
    long i = (long)blockIdx.x * blockDim.x + threadIdx.x;
    long stride = (long)gridDim.x * blockDim.x;
    for (; i < n; i += stride) o[i] = __float2half(in[i]);
}
// [R x C] fp32 -> [C x R] bf16 hi/lo
__global__ void transpose_split_kernel(const float* __restrict__ in,
                                       __nv_bfloat16* __restrict__ hiT,
                                       __nv_bfloat16* __restrict__ loT,
                                       int R, int C) {
    __shared__ float ts[32][33];
    int c0 = blockIdx.x * 32, r0 = blockIdx.y * 32;
    int tx = threadIdx.x & 31, ty = threadIdx.x >> 5;
    for (int rr = ty; rr < 32; rr += 8) {
        int r = r0 + rr, c = c0 + tx;
        ts[rr][tx] = (r < R && c < C) ? in[(size_t)r * C + c] : 0.f;
    }
    __syncthreads();
    for (int cc = ty; cc < 32; cc += 8) {
        int c = c0 + cc, r = r0 + tx;
        if (c < C && r < R) {
            __nv_bfloat16 h, l;
            split_bf(ts[tx][cc], h, l);
            hiT[(size_t)c * R + r] = h;
            loT[(size_t)c * R + r] = l;
        }
    }
}
// [R x C] fp32 -> [C x R] fp16
__global__ void transpose16_kernel(const float* __restrict__ in,
                                   __half* __restrict__ hiT, int R, int C) {
    __shared__ float ts[32][33];
    int c0 = blockIdx.x * 32, r0 = blockIdx.y * 32;
    int tx = threadIdx.x & 31, ty = threadIdx.x >> 5;
    for (int rr = ty; rr < 32; rr += 8) {
        int r = r0 + rr, c = c0 + tx;
        ts[rr][tx] = (r < R && c < C) ? in[(size_t)r * C + c] : 0.f;
    }
    __syncthreads();
    for (int cc = ty; cc < 32; cc += 8) {
        int c = c0 + cc, r = r0 + tx;
        if (c < C && r < R) hiT[(size_t)c * R + r] = __float2half(ts[tx][cc]);
    }
}
__global__ void bc_kernel(const float* __restrict__ b_proj,
                          const float* __restrict__ W_x,
                          const float* __restrict__ b_lstm,
                          float* __restrict__ bc) {
    int n = blockIdx.x * blockDim.x + threadIdx.x;
    if (n >= H4) return;
    float s = b_lstm[n];
    for (int k = 0; k < H_SZ; k++) s += b_proj[k] * W_x[(size_t)k * H4 + n];
    bc[n] = s;
}

// ===================== bf16x3 GEMM (128x128) — Wc only ======================
#define G_SMEM_BYTES (2 * 40960)
__global__ __launch_bounds__(256, 1)
void mma_gemm_bf16(const __nv_bfloat16* __restrict__ Ah, const __nv_bfloat16* __restrict__ Al,
                   const __nv_bfloat16* __restrict__ Bh, const __nv_bfloat16* __restrict__ Bl,
                   __half* __restrict__ C16, int M, int N)
{
    extern __shared__ __align__(16) char smem[];
    const uint32_t sb = smem_u32(smem);
    const int tid = threadIdx.x, lane = tid & 31, wid = tid >> 5;
    const int bm = blockIdx.y * 128, bn = blockIdx.x * 128;
    const int wm = (wid >> 2) * 64, wn = (wid & 3) * 32;

    long a_off[2], b_off[2];
    uint32_t a_s[2], b_s[2], b_sz[2];
#pragma unroll
    for (int q = 0; q < 2; q++) {
        int pos = q * 256 + tid;
        int r = pos >> 2, c8 = (pos & 3) * 8;
        a_off[q] = (long)(bm + r) * H_SZ + c8;
        a_s[q] = (uint32_t)(r * 80 + (pos & 3) * 16);
        int gn = bn + r;
        b_sz[q]  = (gn < N) ? 16u : 0u;
        b_off[q] = (long)((gn < N) ? gn : 0) * H_SZ + c8;
        b_s[q] = a_s[q];
    }

    float acc[4][4][4];
#pragma unroll
    for (int m = 0; m < 4; m++)
#pragma unroll
        for (int j = 0; j < 4; j++)
#pragma unroll
            for (int q = 0; q < 4; q++) acc[m][j][q] = 0.f;

#define GB_LOAD(ck, s) do {                                                   \
    const long ko = (long)(ck) * 32;                                          \
    const uint32_t st = sb + (s) * 40960;                                     \
    _Pragma("unroll")                                                         \
    for (int q = 0; q < 2; q++) {                                             \
        cp16(st + a_s[q],         Ah + a_off[q] + ko, 16u);                   \
        cp16(st + 10240 + a_s[q], Al + a_off[q] + ko, 16u);                   \
        cp16(st + 20480 + b_s[q], Bh + b_off[q] + ko, b_sz[q]);               \
        cp16(st + 30720 + b_s[q], Bl + b_off[q] + ko, b_sz[q]);               \
    }                                                                         \
} while (0)

    GB_LOAD(0, 0); CP_COMMIT();
    GB_LOAD(1, 1); CP_COMMIT();

    for (int ck = 0; ck < 32; ck++) {
        const int s = ck & 1;
        CP_WAIT1();
        __syncthreads();
        const uint32_t sA = sb + s * 40960;
        const uint32_t sB = sA + 20480;
#pragma unroll
        for (int ks = 0; ks < 2; ks++) {
            uint32_t ah[4][4], al[4][4], bh[8], bl[8];
            const int arow = lane & 15;
            const uint32_t ac = (uint32_t)(((lane >> 4) * 8 + ks * 16) * 2);
#pragma unroll
            for (int mf = 0; mf < 4; mf++) {
                uint32_t ad = sA + (uint32_t)((wm + mf * 16 + arow) * 80) + ac;
                ldsm4(ah[mf], ad);
                ldsm4(al[mf], ad + 10240);
            }
            const int brow = (lane & 7) + ((lane >> 4) & 1) * 8;
            const uint32_t bcd = (uint32_t)(((((lane >> 3) & 1) * 8) + ks * 16) * 2);
#pragma unroll
            for (int pf = 0; pf < 2; pf++) {
                uint32_t bd = sB + (uint32_t)((wn + pf * 16 + brow) * 80) + bcd;
                ldsm4(&bh[pf * 4], bd);
                ldsm4(&bl[pf * 4], bd + 10240);
            }
#pragma unroll
            for (int m = 0; m < 4; m++)
#pragma unroll
                for (int j = 0; j < 4; j++) {
                    const int bi = (j >> 1) * 4 + (j & 1) * 2;
                    mma_bf16(acc[m][j], ah[m], bh[bi], bh[bi + 1]);
                    mma_bf16(acc[m][j], al[m], bh[bi], bh[bi + 1]);
                    mma_bf16(acc[m][j], ah[m], bl[bi], bl[bi + 1]);
                }
        }
        __syncthreads();
        if (ck + 2 < 32) GB_LOAD(ck + 2, s);
        CP_COMMIT();
    }

#pragma unroll
    for (int m = 0; m < 4; m++) {
        const int r0 = bm + wm + m * 16 + (lane >> 2);
#pragma unroll
        for (int j = 0; j < 4; j++) {
            const int col = bn + wn + j * 8 + (lane & 3) * 2;
#pragma unroll
            for (int hh = 0; hh < 2; hh++) {
                const int r = r0 + hh * 8;
                if (col < N)     C16[(size_t)r * N + col]     = __float2half(acc[m][j][hh * 2 + 0]);
                if (col + 1 < N) C16[(size_t)r * N + col + 1] = __float2half(acc[m][j][hh * 2 + 1]);
            }
        }
    }
#undef GB_LOAD
}

// ===================== fp16 GEMM (128x256), single A-pass, 2-stage ==========
// C[M,N] = Ah[M,1024] @ Bh[N,1024]^T + bias.  M arbitrary (A rows clamped).
__global__ __launch_bounds__(256, 1)
void mma_gemm_f16(const __half* __restrict__ Ah,
                  const __half* __restrict__ Bh,
                  const float* __restrict__ bias,
                  float* __restrict__ C, int M, int N)
{
    extern __shared__ __align__(16) char smem[];
    const uint32_t sb = smem_u32(smem);
    const int tid = threadIdx.x, lane = tid & 31, wid = tid >> 5;
    const int bm = blockIdx.y * 128, bn = blockIdx.x * 256;
    const int wm = (wid >> 2) * 64, wn = (wid & 3) * 64;

    long a_off[2];
    uint32_t a_s[2];
#pragma unroll
    for (int q = 0; q < 2; q++) {
        int pos = q * 256 + tid;
        int r = pos >> 2, c8 = (pos & 3) * 8;
        int ar = bm + r; if (ar >= M) ar = M - 1;       // M-clamp
        a_off[q] = (long)ar * H_SZ + c8;
        a_s[q] = (uint32_t)(r * 80 + (pos & 3) * 16);
    }
    long b_off[4];
    uint32_t b_s[4], b_sz[4];
#pragma unroll
    for (int q = 0; q < 4; q++) {
        int pos = q * 256 + tid;
        int r = pos >> 2, c8 = (pos & 3) * 8;
        int gn = bn + r;
        b_sz[q]  = (gn < N) ? 16u : 0u;
        b_off[q] = (long)((gn < N) ? gn : 0) * H_SZ + c8;
        b_s[q] = (uint32_t)(r * 80 + (pos & 3) * 16);
    }

    float acc[4][8][4];
#pragma unroll
    for (int m = 0; m < 4; m++)
#pragma unroll
        for (int j = 0; j < 8; j++)
#pragma unroll
            for (int q = 0; q < 4; q++) acc[m][j][q] = 0.f;

#define G2_LOAD(ck, s) do {                                                   \
    const long ko = (long)(ck) * 32;                                          \
    const uint32_t st = sb + (s) * 30720;                                     \
    _Pragma("unroll")                                                         \
    for (int q = 0; q < 2; q++)                                               \
        cp16(st + a_s[q], Ah + a_off[q] + ko, 16u);                           \
    _Pragma("unroll")                                                         \
    for (int q = 0; q < 4; q++)                                               \
        cp16(st + 10240 + b_s[q], Bh + b_off[q] + ko, b_sz[q]);               \
} while (0)

    G2_LOAD(0, 0); CP_COMMIT();
    G2_LOAD(1, 1); CP_COMMIT();

    for (int ck = 0; ck < 32; ck++) {
        const int s = ck & 1;
        CP_WAIT1();
        __syncthreads();
        const uint32_t sA = sb + s * 30720;
        const uint32_t sB = sA + 10240;
#pragma unroll
        for (int ks = 0; ks < 2; ks++) {
            uint32_t ah[4][4], bh[16];
            const int arow = lane & 15;
            const uint32_t ac = (uint32_t)(((lane >> 4) * 8 + ks * 16) * 2);
#pragma unroll
            for (int mf = 0; mf < 4; mf++) {
                uint32_t ad = sA + (uint32_t)((wm + mf * 16 + arow) * 80) + ac;
                ldsm4(ah[mf], ad);
            }
            const int brow = (lane & 7) + ((lane >> 4) & 1) * 8;
            const uint32_t bcd = (uint32_t)(((((lane >> 3) & 1) * 8) + ks * 16) * 2);
#pragma unroll
            for (int pf = 0; pf < 4; pf++) {
                uint32_t bd = sB + (uint32_t)((wn + pf * 16 + brow) * 80) + bcd;
                ldsm4(&bh[pf * 4], bd);
            }
#pragma unroll
            for (int m = 0; m < 4; m++)
#pragma unroll
                for (int j = 0; j < 8; j++) {
                    const int bi = (j >> 1) * 4 + (j & 1) * 2;
                    mma_f16(acc[m][j], ah[m], bh[bi], bh[bi + 1]);
                }
        }
        __syncthreads();
        if (ck + 2 < 32) G2_LOAD(ck + 2, s);
        CP_COMMIT();
    }

#pragma unroll
    for (int m = 0; m < 4; m++) {
        const int r0 = bm + wm + m * 16 + (lane >> 2);
#pragma unroll
        for (int j = 0; j < 8; j++) {
            const int col = bn + wn + j * 8 + (lane & 3) * 2;
#pragma unroll
            for (int hh = 0; hh < 2; hh++) {
                const int r = r0 + hh * 8;
                if (col < N)     C[(size_t)r * N + col]     = acc[m][j][hh * 2 + 0] + bias[col];
                if (col + 1 < N) C[(size_t)r * N + col + 1] = acc[m][j][hh * 2 + 1] + bias[col + 1];
            }
        }
    }
#undef G2_LOAD
}

// ===================== persistent LSTM scan (8 warps, K-split) ==============
// ONE kernel, 256 timesteps, 128 CTAs x 256 threads. Grid barrier per step is
// ATOMIC-FREE: per-CTA flag words (monotonic step counts), plain volatile
// store to own flag + 128 parallel volatile loads — no L2 RMW serialization.
#define A_BYTES   (32 * 2560)            // 32 chunks x (32 rows x 80 B)
#define SB_STG    5120                   // 64 rows x 80 B
#define RING_BYTES (4 * SB_STG)          // per-quad ring
#define SCAN_SMEM (A_BYTES + 2 * RING_BYTES)   // 122880 B

__global__ __launch_bounds__(256, 1)
void lstm_scan_persistent(const __half* __restrict__ WhT16,
                          const float* __restrict__ pxv,   // [V, 4H]
                          const int* __restrict__ xidx,    // [T, B]
                          const float* __restrict__ c_in,
                          __half* __restrict__ res,        // (T+1) slabs [B,H]
                          float* __restrict__ hf, float* __restrict__ cf)
{
    extern __shared__ __align__(16) char smem[];
    const uint32_t sb = smem_u32(smem);
    const int tid = threadIdx.x, lane = tid & 31, wid = tid >> 5;
    const int half = wid >> 2;                 // K-half: 0 or 1
    const int wq = wid & 3;                    // warp within quad
    const int u0 = blockIdx.x * 8;
    const int wm = (wq >> 1) * 16, wn = (wq & 1) * 32;

    // ---- load W_h slice into persistent SMEM (once; 256 threads) ----
    for (int idx = tid; idx < 4096; idx += 256) {
        int ck = idx >> 7, pos = idx & 127;
        int r = pos >> 2, seg = pos & 3;
        long grow = (long)(r >> 3) * H_SZ + u0 + (r & 7);   // gate*H + unit
        const __half* src = WhT16 + grow * H_SZ + ck * 32 + seg * 8;
        cp16(sb + (uint32_t)(ck * 2560 + r * 80 + seg * 16), src, 16u);
    }
    CP_COMMIT();

    // ---- c into registers: thread = (u in 0..7) x (2 batch rows) ----
    const int u = tid & 7;
    const int b0 = (tid >> 3) * 2;             // 0..62
    const int gu = u0 + u;
    float creg[2];
#pragma unroll
    for (int jj = 0; jj < 2; jj++) creg[jj] = c_in[(b0 + jj) * H_SZ + gu];

    // B-operand descriptors (per-quad: 128 threads cover a 64x80B stage)
    const int htid = tid & 127;
    uint32_t b_s[2];
    long b_row[2];
#pragma unroll
    for (int q = 0; q < 2; q++) {
        int pos = q * 128 + htid;
        int r = pos >> 2, c8 = (pos & 3) * 8;
        b_row[q] = (long)r * H_SZ + c8;
        b_s[q] = (uint32_t)(r * 80 + (pos & 3) * 16);
    }
    const uint32_t ringb = sb + A_BYTES + (uint32_t)half * RING_BYTES;
    float* Gs0 = (float*)(smem + A_BYTES);
    float* Gs1 = (float*)(smem + A_BYTES + 8320);
    float* GsH = half ? Gs1 : Gs0;

    CP_WAIT0();
    __syncthreads();   // W_h slice ready

#define SB_LOAD(hhp, ck, s) do {                                              \
    const long ko = (long)(ck) * 32;                                          \
    const uint32_t st = ringb + (s) * SB_STG;                                 \
    _Pragma("unroll")                                                         \
    for (int q = 0; q < 2; q++)                                               \
        cp16(st + b_s[q], (hhp) + b_row[q] + ko, 16u);                        \
} while (0)

    const int ck0 = half * 16;                 // this quad's first K chunk

    for (int t = 0; t < T_STEPS; t++) {
        const __half* hh = res + (size_t)t * BH;
        __half*       oh = res + (size_t)(t + 1) * BH;

        // px gate prefetch via vocab gather (hidden behind the K-loop)
        float pr[2][4];
#pragma unroll
        for (int jj = 0; jj < 2; jj++) {
            const int row = xidx[t * B_SZ + b0 + jj];
            const float* pxb = pxv + (size_t)row * H4;
            pr[jj][0] = pxb[gu];
            pr[jj][1] = pxb[1024 + gu];
            pr[jj][2] = pxb[2048 + gu];
            pr[jj][3] = pxb[3072 + gu];
        }

        float acc[4][4];
#pragma unroll
        for (int j = 0; j < 4; j++)
#pragma unroll
            for (int q = 0; q < 4; q++) acc[j][q] = 0.f;

        SB_LOAD(hh, ck0 + 0, 0); CP_COMMIT();
        SB_LOAD(hh, ck0 + 1, 1); CP_COMMIT();
        SB_LOAD(hh, ck0 + 2, 2); CP_COMMIT();

        for (int i = 0; i < 16; i++) {
            const int s = i & 3;
            CP_WAIT2();
            BAR_SYNC(1 + half, 128);           // quad-local barrier
            const uint32_t sA = sb + (uint32_t)((ck0 + i) * 2560);
            const uint32_t sB = ringb + s * SB_STG;
#pragma unroll
            for (int ks = 0; ks < 2; ks++) {
                uint32_t ah[4], bh[8];
                const uint32_t ac = (uint32_t)(((lane >> 4) * 8 + ks * 16) * 2);
                ldsm4(ah, sA + (uint32_t)((wm + (lane & 15)) * 80) + ac);
                const int brow = (lane & 7) + ((lane >> 4) & 1) * 8;
                const uint32_t bcd = (uint32_t)(((((lane >> 3) & 1) * 8) + ks * 16) * 2);
#pragma unroll
                for (int pf = 0; pf < 2; pf++) {
                    uint32_t bd = sB + (uint32_t)((wn + pf * 16 + brow) * 80) + bcd;
                    ldsm4(&bh[pf * 4], bd);
                }
#pragma unroll
                for (int j = 0; j < 4; j++) {
                    const int bi = (j >> 1) * 4 + (j & 1) * 2;
                    mma_f16(acc[j], ah, bh[bi], bh[bi + 1]);
                }
            }
            if (i + 3 < 16) { SB_LOAD(hh, ck0 + i + 3, (i + 3) & 3); }
            CP_COMMIT();
        }

        __syncthreads();   // both quads done; Gs may overwrite ring area
        {
            const int row = wm + (lane >> 2);
#pragma unroll
            for (int j = 0; j < 4; j++) {
                const int col = wn + j * 8 + (lane & 3) * 2;
                GsH[row * 65 + col]           = acc[j][0];
                GsH[row * 65 + col + 1]       = acc[j][1];
                GsH[(row + 8) * 65 + col]     = acc[j][2];
                GsH[(row + 8) * 65 + col + 1] = acc[j][3];
            }
        }
        __syncthreads();

#pragma unroll
        for (int jj = 0; jj < 2; jj++) {
            const int b = b0 + jj;
            float gi = Gs0[(0 * 8 + u) * 65 + b] + Gs1[(0 * 8 + u) * 65 + b] + pr[jj][0];
            float gf = Gs0[(1 * 8 + u) * 65 + b] + Gs1[(1 * 8 + u) * 65 + b] + pr[jj][1];
            float gg = Gs0[(2 * 8 + u) * 65 + b] + Gs1[(2 * 8 + u) * 65 + b] + pr[jj][2];
            float go = Gs0[(3 * 8 + u) * 65 + b] + Gs1[(3 * 8 + u) * 65 + b] + pr[jj][3];
            float si = 1.f / (1.f + expf(-gi));
            float sf = 1.f / (1.f + expf(-gf));
            float so = 1.f / (1.f + expf(-go));
            float tg = tanhf(gg);
            float cn = sf * creg[jj] + si * tg;
            float hn = so * tanhf(cn);
            creg[jj] = cn;
            const int ci = b * H_SZ + gu;
            oh[ci] = __float2half(hn);
            if (t == T_STEPS - 1) { hf[ci] = hn; cf[ci] = cn; }
        }

        // ---- atomic-free grid barrier: per-CTA flag + parallel polling ----
        if (t < T_STEPS - 1) {
            __threadfence();                       // h writes visible device-wide
            __syncthreads();                       // whole CTA arrived
            if (tid == 0)
                ((volatile unsigned*)g_flags)[blockIdx.x] = (unsigned)(t + 1);
            if (tid < SCAN_CTAS) {
                volatile unsigned* f = (volatile unsigned*)g_flags + tid;
                while (*f < (unsigned)(t + 1)) { }
            }
            __syncthreads();
            __threadfence();                       // acquire side
        }
    }
#undef SB_LOAD
}

// ===================== launch ================================================
extern "C" void kernel_launch(void* const* d_in, const int* in_sizes, int n_in,
                              void* d_out, int out_size)
{
    const int*   x      = (const int*)  d_in[0];
    const float* h      = (const float*)d_in[1];
    const float* c      = (const float*)d_in[2];
    const float* emb    = (const float*)d_in[3];
    const float* W_proj = (const float*)d_in[4];
    const float* b_proj = (const float*)d_in[5];
    const float* W_x    = (const float*)d_in[6];
    const float* W_h    = (const float*)d_in[7];
    const float* b_lstm = (const float*)d_in[8];
    const float* W_out  = (const float*)d_in[9];
    const float* b_out  = (const float*)d_in[10];
    float* out = (float*)d_out;

    float *pxv, *bc;
    unsigned int* flags;
    __nv_bfloat16 *wxth, *wxtl, *wph, *wpl;
    __half *r16h, *e16h, *wht16, *wot16, *wct16;
    cudaGetSymbolAddress((void**)&pxv,   g_px);
    cudaGetSymbolAddress((void**)&bc,    g_bc);
    cudaGetSymbolAddress((void**)&flags, g_flags);
    cudaGetSymbolAddress((void**)&r16h,  g_res16h);
    cudaGetSymbolAddress((void**)&e16h,  g_emb16h);
    cudaGetSymbolAddress((void**)&wxth,  g_WxT_hi);
    cudaGetSymbolAddress((void**)&wxtl,  g_WxT_lo);
    cudaGetSymbolAddress((void**)&wht16, g_WhT16);
    cudaGetSymbolAddress((void**)&wot16, g_WoT16);
    cudaGetSymbolAddress((void**)&wph,   g_Wp_hi);
    cudaGetSymbolAddress((void**)&wpl,   g_Wp_lo);
    cudaGetSymbolAddress((void**)&wct16, g_WcT16);

    cudaFuncSetAttribute(mma_gemm_bf16,
                         cudaFuncAttributeMaxDynamicSharedMemorySize, G_SMEM_BYTES);
    cudaFuncSetAttribute(mma_gemm_f16,
                         cudaFuncAttributeMaxDynamicSharedMemorySize, 2 * 30720);
    cudaFuncSetAttribute(lstm_scan_persistent,
                         cudaFuncAttributeMaxDynamicSharedMemorySize, SCAN_SMEM);

    // ---------- prepass ----------
    cudaMemsetAsync(flags, 0, SCAN_CTAS * sizeof(unsigned int), 0);
    split_kernel<<<512, 256>>>(W_proj, wph, wpl, (long)H_SZ * H_SZ);
    conv16_kernel<<<2048, 256>>>(emb, e16h, (long)O_SZ * H_SZ);
    conv16_kernel<<<64, 256>>>(h, r16h, (long)BH);   // slab 0 = h_{-1}
    transpose_split_kernel<<<dim3(H4 / 32, H_SZ / 32), 256>>>(W_x, wxth, wxtl, H_SZ, H4);
    transpose16_kernel<<<dim3(H4 / 32, H_SZ / 32), 256>>>(W_h, wht16, H_SZ, H4);
    transpose16_kernel<<<dim3((O_SZ + 31) / 32, H_SZ / 32), 256>>>(W_out, wot16, H_SZ, O_SZ);
    bc_kernel<<<(H4 + 255) / 256, 256>>>(b_proj, W_x, b_lstm, bc);

    // ---------- Wc = (W_proj @ W_x)^T  (bf16x3, fp16 out) ----------
    mma_gemm_bf16<<<dim3(H_SZ / 128, H4 / 128), 256, G_SMEM_BYTES>>>(
        wxth, wxtl, wph, wpl, wct16, H4, H_SZ);

    // ---------- pxv = emb @ WcT^T + bc over the VOCABULARY  [V, 4H] ----------
    mma_gemm_f16<<<dim3(H4 / 256, (V_SZ + 127) / 128), 256, 2 * 30720>>>(
        e16h, wct16, bc, pxv, V_SZ, H4);

    // ---------- persistent LSTM scan (gathers pxv[x[t,b]]) ----------
    float* hf_out = out + (size_t)TB * O_SZ;
    float* cf_out = hf_out + BH;
    lstm_scan_persistent<<<SCAN_CTAS, 256, SCAN_SMEM>>>(
        wht16, pxv, x, c, r16h, hf_out, cf_out);

    // ---------- out = res @ W_out^T + b_out  (single launch) ----------
    mma_gemm_f16<<<dim3((O_SZ + 255) / 256, TB / 128), 256, 2 * 30720>>>(
        r16h + BH, wot16, b_out, out, TB, O_SZ);
}

// round 14
// speedup vs baseline: 1.4064x; 1.4064x over previous
#include <cuda_runtime.h>
#include <cuda_bf16.h>
#include <cuda_fp16.h>
#include <cstdint>
#include <math.h>

#define T_STEPS 256
#define B_SZ 64
#define H_SZ 1024
#define H4 4096
#define O_SZ 10000
#define V_SZ 10000
#define TB (T_STEPS * B_SZ)
#define BH (B_SZ * H_SZ)

// ===================== low-level helpers (sm_80+ features only) =============
__device__ __forceinline__ uint32_t smem_u32(const void* p) {
    uint32_t a;
    asm("{ .reg .u64 t; cvta.to.shared.u64 t, %1; cvt.u32.u64 %0, t; }"
        : "=r"(a) : "l"(p));
    return a;
}
__device__ __forceinline__ void ldsm4(uint32_t* r, uint32_t a) {
    asm volatile("ldmatrix.sync.aligned.m8n8.x4.shared.b16 {%0,%1,%2,%3}, [%4];"
                 : "=r"(r[0]), "=r"(r[1]), "=r"(r[2]), "=r"(r[3]) : "r"(a));
}
__device__ __forceinline__ void mma_bf16(float* c, const uint32_t* a,
                                         uint32_t b0, uint32_t b1) {
    asm volatile(
        "mma.sync.aligned.m16n8k16.row.col.f32.bf16.bf16.f32 "
        "{%0,%1,%2,%3}, {%4,%5,%6,%7}, {%8,%9}, {%0,%1,%2,%3};"
        : "+f"(c[0]), "+f"(c[1]), "+f"(c[2]), "+f"(c[3])
        : "r"(a[0]), "r"(a[1]), "r"(a[2]), "r"(a[3]), "r"(b0), "r"(b1));
}
__device__ __forceinline__ void mma_f16(float* c, const uint32_t* a,
                                        uint32_t b0, uint32_t b1) {
    asm volatile(
        "mma.sync.aligned.m16n8k16.row.col.f32.f16.f16.f32 "
        "{%0,%1,%2,%3}, {%4,%5,%6,%7}, {%8,%9}, {%0,%1,%2,%3};"
        : "+f"(c[0]), "+f"(c[1]), "+f"(c[2]), "+f"(c[3])
        : "r"(a[0]), "r"(a[1]), "r"(a[2]), "r"(a[3]), "r"(b0), "r"(b1));
}
__device__ __forceinline__ void cp16(uint32_t dst, const void* src, uint32_t sz) {
    asm volatile("cp.async.cg.shared.global [%0], [%1], 16, %2;"
                 :: "r"(dst), "l"(src), "r"(sz) : "memory");
}
#define CP_COMMIT() asm volatile("cp.async.commit_group;" ::: "memory")
#define CP_WAIT0()  asm volatile("cp.async.wait_group 0;" ::: "memory")
#define CP_WAIT1()  asm volatile("cp.async.wait_group 1;" ::: "memory")
#define CP_WAIT2()  asm volatile("cp.async.wait_group 2;" ::: "memory")
#define BAR_SYNC(id, n) asm volatile("bar.sync %0, %1;" :: "r"(id), "r"(n) : "memory")

__device__ __forceinline__ void split_bf(float x, __nv_bfloat16& hi, __nv_bfloat16& lo) {
    hi = __float2bfloat16(x);
    lo = __float2bfloat16(x - __bfloat162float(hi));
}
// fast sigmoid/tanh (MUFU ex2+rcp; rel err ~1e-6, negligible vs 3.5e-4 budget)
__device__ __forceinline__ float fsig(float x) {
    return __fdividef(1.f, 1.f + __expf(-x));
}
__device__ __forceinline__ float ftanh(float x) {
    return 1.f - __fdividef(2.f, __expf(2.f * x) + 1.f);
}

// ===================== scratch (device globals) ==============================
#define SCAN_CTAS 128
__device__ float          g_px[(size_t)TB * H4];   // holds pxv[V(+pad), 4H]
__device__ float          g_bc[H4];
__device__ unsigned int   g_bar;
__device__ __half         g_res16h[(size_t)(T_STEPS + 1) * BH];
__device__ __half         g_emb16h[(size_t)O_SZ * H_SZ];
__device__ __nv_bfloat16  g_WxT_hi[(size_t)H4 * H_SZ],   g_WxT_lo[(size_t)H4 * H_SZ];
__device__ __half         g_WhT16[(size_t)H4 * H_SZ];
__device__ __half         g_WoT16[(size_t)O_SZ * H_SZ];
__device__ __nv_bfloat16  g_Wp_hi[(size_t)H_SZ * H_SZ],  g_Wp_lo[(size_t)H_SZ * H_SZ];
__device__ __half         g_WcT16[(size_t)H4 * H_SZ];

// ===================== pre-pass kernels ======================================
__global__ void split_kernel(const float* __restrict__ in,
                             __nv_bfloat16* __restrict__ hi,
                             __nv_bfloat16* __restrict__ lo, long n) {
    long i = (long)blockIdx.x * blockDim.x + threadIdx.x;
    long stride = (long)gridDim.x * blockDim.x;
    for (; i < n; i += stride) split_bf(in[i], hi[i], lo[i]);
}
__global__ void conv16_kernel(const float* __restrict__ in,
                              __half* __restrict__ o, long n) {
    long i = (long)blockIdx.x * blockDim.x + threadIdx.x;
    long stride = (long)gridDim.x * blockDim.x;
    for (; i < n; i += stride) o[i] = __float2half(in[i]);
}
// [R x C] fp32 -> [C x R] bf16 hi/lo
__global__ void transpose_split_kernel(const float* __restrict__ in,
                                       __nv_bfloat16* __restrict__ hiT,
                                       __nv_bfloat16* __restrict__ loT,
                                       int R, int C) {
    __shared__ float ts[32][33];
    int c0 = blockIdx.x * 32, r0 = blockIdx.y * 32;
    int tx = threadIdx.x & 31, ty = threadIdx.x >> 5;
    for (int rr = ty; rr < 32; rr += 8) {
        int r = r0 + rr, c = c0 + tx;
        ts[rr][tx] = (r < R && c < C) ? in[(size_t)r * C + c] : 0.f;
    }
    __syncthreads();
    for (int cc = ty; cc < 32; cc += 8) {
        int c = c0 + cc, r = r0 + tx;
        if (c < C && r < R) {
            __nv_bfloat16 h, l;
            split_bf(ts[tx][cc], h, l);
            hiT[(size_t)c * R + r] = h;
            loT[(size_t)c * R + r] = l;
        }
    }
}
// [R x C] fp32 -> [C x R] fp16
__global__ void transpose16_kernel(const float* __restrict__ in,
                                   __half* __restrict__ hiT, int R, int C) {
    __shared__ float ts[32][33];
    int c0 = blockIdx.x * 32, r0 = blockIdx.y * 32;
    int tx = threadIdx.x & 31, ty = threadIdx.x >> 5;
    for (int rr = ty; rr < 32; rr += 8) {
        int r = r0 + rr, c = c0 + tx;
        ts[rr][tx] = (r < R && c < C) ? in[(size_t)r * C + c] : 0.f;
    }
    __syncthreads();
    for (int cc = ty; cc < 32; cc += 8) {
        int c = c0 + cc, r = r0 + tx;
        if (c < C && r < R) hiT[(size_t)c * R + r] = __float2half(ts[tx][cc]);
    }
}
__global__ void bc_kernel(const float* __restrict__ b_proj,
                          const float* __restrict__ W_x,
                          const float* __restrict__ b_lstm,
                          float* __restrict__ bc) {
    int n = blockIdx.x * blockDim.x + threadIdx.x;
    if (n >= H4) return;
    float s = b_lstm[n];
    for (int k = 0; k < H_SZ; k++) s += b_proj[k] * W_x[(size_t)k * H4 + n];
    bc[n] = s;
}

// ===================== bf16x3 GEMM (128x128) — Wc only ======================
#define G_SMEM_BYTES (2 * 40960)
__global__ __launch_bounds__(256, 1)
void mma_gemm_bf16(const __nv_bfloat16* __restrict__ Ah, const __nv_bfloat16* __restrict__ Al,
                   const __nv_bfloat16* __restrict__ Bh, const __nv_bfloat16* __restrict__ Bl,
                   __half* __restrict__ C16, int M, int N)
{
    extern __shared__ __align__(16) char smem[];
    const uint32_t sb = smem_u32(smem);
    const int tid = threadIdx.x, lane = tid & 31, wid = tid >> 5;
    const int bm = blockIdx.y * 128, bn = blockIdx.x * 128;
    const int wm = (wid >> 2) * 64, wn = (wid & 3) * 32;

    long a_off[2], b_off[2];
    uint32_t a_s[2], b_s[2], b_sz[2];
#pragma unroll
    for (int q = 0; q < 2; q++) {
        int pos = q * 256 + tid;
        int r = pos >> 2, c8 = (pos & 3) * 8;
        a_off[q] = (long)(bm + r) * H_SZ + c8;
        a_s[q] = (uint32_t)(r * 80 + (pos & 3) * 16);
        int gn = bn + r;
        b_sz[q]  = (gn < N) ? 16u : 0u;
        b_off[q] = (long)((gn < N) ? gn : 0) * H_SZ + c8;
        b_s[q] = a_s[q];
    }

    float acc[4][4][4];
#pragma unroll
    for (int m = 0; m < 4; m++)
#pragma unroll
        for (int j = 0; j < 4; j++)
#pragma unroll
            for (int q = 0; q < 4; q++) acc[m][j][q] = 0.f;

#define GB_LOAD(ck, s) do {                                                   \
    const long ko = (long)(ck) * 32;                                          \
    const uint32_t st = sb + (s) * 40960;                                     \
    _Pragma("unroll")                                                         \
    for (int q = 0; q < 2; q++) {                                             \
        cp16(st + a_s[q],         Ah + a_off[q] + ko, 16u);                   \
        cp16(st + 10240 + a_s[q], Al + a_off[q] + ko, 16u);                   \
        cp16(st + 20480 + b_s[q], Bh + b_off[q] + ko, b_sz[q]);               \
        cp16(st + 30720 + b_s[q], Bl + b_off[q] + ko, b_sz[q]);               \
    }                                                                         \
} while (0)

    GB_LOAD(0, 0); CP_COMMIT();
    GB_LOAD(1, 1); CP_COMMIT();

    for (int ck = 0; ck < 32; ck++) {
        const int s = ck & 1;
        CP_WAIT1();
        __syncthreads();
        const uint32_t sA = sb + s * 40960;
        const uint32_t sB = sA + 20480;
#pragma unroll
        for (int ks = 0; ks < 2; ks++) {
            uint32_t ah[4][4], al[4][4], bh[8], bl[8];
            const int arow = lane & 15;
            const uint32_t ac = (uint32_t)(((lane >> 4) * 8 + ks * 16) * 2);
#pragma unroll
            for (int mf = 0; mf < 4; mf++) {
                uint32_t ad = sA + (uint32_t)((wm + mf * 16 + arow) * 80) + ac;
                ldsm4(ah[mf], ad);
                ldsm4(al[mf], ad + 10240);
            }
            const int brow = (lane & 7) + ((lane >> 4) & 1) * 8;
            const uint32_t bcd = (uint32_t)(((((lane >> 3) & 1) * 8) + ks * 16) * 2);
#pragma unroll
            for (int pf = 0; pf < 2; pf++) {
                uint32_t bd = sB + (uint32_t)((wn + pf * 16 + brow) * 80) + bcd;
                ldsm4(&bh[pf * 4], bd);
                ldsm4(&bl[pf * 4], bd + 10240);
            }
#pragma unroll
            for (int m = 0; m < 4; m++)
#pragma unroll
                for (int j = 0; j < 4; j++) {
                    const int bi = (j >> 1) * 4 + (j & 1) * 2;
                    mma_bf16(acc[m][j], ah[m], bh[bi], bh[bi + 1]);
                    mma_bf16(acc[m][j], al[m], bh[bi], bh[bi + 1]);
                    mma_bf16(acc[m][j], ah[m], bl[bi], bl[bi + 1]);
                }
        }
        __syncthreads();
        if (ck + 2 < 32) GB_LOAD(ck + 2, s);
        CP_COMMIT();
    }

#pragma unroll
    for (int m = 0; m < 4; m++) {
        const int r0 = bm + wm + m * 16 + (lane >> 2);
#pragma unroll
        for (int j = 0; j < 4; j++) {
            const int col = bn + wn + j * 8 + (lane & 3) * 2;
#pragma unroll
            for (int hh = 0; hh < 2; hh++) {
                const int r = r0 + hh * 8;
                if (col < N)     C16[(size_t)r * N + col]     = __float2half(acc[m][j][hh * 2 + 0]);
                if (col + 1 < N) C16[(size_t)r * N + col + 1] = __float2half(acc[m][j][hh * 2 + 1]);
            }
        }
    }
#undef GB_LOAD
}

// ===================== fp16 GEMM (128x256), single A-pass, 2-stage ==========
// C[M,N] = Ah[M,1024] @ Bh[N,1024]^T + bias.  M arbitrary (A rows clamped).
__global__ __launch_bounds__(256, 1)
void mma_gemm_f16(const __half* __restrict__ Ah,
                  const __half* __restrict__ Bh,
                  const float* __restrict__ bias,
                  float* __restrict__ C, int M, int N)
{
    extern __shared__ __align__(16) char smem[];
    const uint32_t sb = smem_u32(smem);
    const int tid = threadIdx.x, lane = tid & 31, wid = tid >> 5;
    const int bm = blockIdx.y * 128, bn = blockIdx.x * 256;
    const int wm = (wid >> 2) * 64, wn = (wid & 3) * 64;

    long a_off[2];
    uint32_t a_s[2];
#pragma unroll
    for (int q = 0; q < 2; q++) {
        int pos = q * 256 + tid;
        int r = pos >> 2, c8 = (pos & 3) * 8;
        int ar = bm + r; if (ar >= M) ar = M - 1;       // M-clamp
        a_off[q] = (long)ar * H_SZ + c8;
        a_s[q] = (uint32_t)(r * 80 + (pos & 3) * 16);
    }
    long b_off[4];
    uint32_t b_s[4], b_sz[4];
#pragma unroll
    for (int q = 0; q < 4; q++) {
        int pos = q * 256 + tid;
        int r = pos >> 2, c8 = (pos & 3) * 8;
        int gn = bn + r;
        b_sz[q]  = (gn < N) ? 16u : 0u;
        b_off[q] = (long)((gn < N) ? gn : 0) * H_SZ + c8;
        b_s[q] = (uint32_t)(r * 80 + (pos & 3) * 16);
    }

    float acc[4][8][4];
#pragma unroll
    for (int m = 0; m < 4; m++)
#pragma unroll
        for (int j = 0; j < 8; j++)
#pragma unroll
            for (int q = 0; q < 4; q++) acc[m][j][q] = 0.f;

#define G2_LOAD(ck, s) do {                                                   \
    const long ko = (long)(ck) * 32;                                          \
    const uint32_t st = sb + (s) * 30720;                                     \
    _Pragma("unroll")                                                         \
    for (int q = 0; q < 2; q++)                                               \
        cp16(st + a_s[q], Ah + a_off[q] + ko, 16u);                           \
    _Pragma("unroll")                                                         \
    for (int q = 0; q < 4; q++)                                               \
        cp16(st + 10240 + b_s[q], Bh + b_off[q] + ko, b_sz[q]);               \
} while (0)

    G2_LOAD(0, 0); CP_COMMIT();
    G2_LOAD(1, 1); CP_COMMIT();

    for (int ck = 0; ck < 32; ck++) {
        const int s = ck & 1;
        CP_WAIT1();
        __syncthreads();
        const uint32_t sA = sb + s * 30720;
        const uint32_t sB = sA + 10240;
#pragma unroll
        for (int ks = 0; ks < 2; ks++) {
            uint32_t ah[4][4], bh[16];
            const int arow = lane & 15;
            const uint32_t ac = (uint32_t)(((lane >> 4) * 8 + ks * 16) * 2);
#pragma unroll
            for (int mf = 0; mf < 4; mf++) {
                uint32_t ad = sA + (uint32_t)((wm + mf * 16 + arow) * 80) + ac;
                ldsm4(ah[mf], ad);
            }
            const int brow = (lane & 7) + ((lane >> 4) & 1) * 8;
            const uint32_t bcd = (uint32_t)(((((lane >> 3) & 1) * 8) + ks * 16) * 2);
#pragma unroll
            for (int pf = 0; pf < 4; pf++) {
                uint32_t bd = sB + (uint32_t)((wn + pf * 16 + brow) * 80) + bcd;
                ldsm4(&bh[pf * 4], bd);
            }
#pragma unroll
            for (int m = 0; m < 4; m++)
#pragma unroll
                for (int j = 0; j < 8; j++) {
                    const int bi = (j >> 1) * 4 + (j & 1) * 2;
                    mma_f16(acc[m][j], ah[m], bh[bi], bh[bi + 1]);
                }
        }
        __syncthreads();
        if (ck + 2 < 32) G2_LOAD(ck + 2, s);
        CP_COMMIT();
    }

#pragma unroll
    for (int m = 0; m < 4; m++) {
        const int r0 = bm + wm + m * 16 + (lane >> 2);
#pragma unroll
        for (int j = 0; j < 8; j++) {
            const int col = bn + wn + j * 8 + (lane & 3) * 2;
#pragma unroll
            for (int hh = 0; hh < 2; hh++) {
                const int r = r0 + hh * 8;
                if (col < N)     C[(size_t)r * N + col]     = acc[m][j][hh * 2 + 0] + bias[col];
                if (col + 1 < N) C[(size_t)r * N + col + 1] = acc[m][j][hh * 2 + 1] + bias[col + 1];
            }
        }
    }
#undef G2_LOAD
}

// ===================== persistent LSTM scan (8 warps, K-split) ==============
// ONE kernel, 256 timesteps, 128 CTAs x 256 threads. R12 single-counter grid
// barrier (proven best). Gs1 lives in quad-1's own ring so each quad's gate
// write needs only its quad-local barrier (one full __syncthreads saved).
#define A_BYTES   (32 * 2560)            // 32 chunks x (32 rows x 80 B)
#define SB_STG    5120                   // 64 rows x 80 B
#define RING_BYTES (4 * SB_STG)          // per-quad ring
#define SCAN_SMEM (A_BYTES + 2 * RING_BYTES)   // 122880 B

__global__ __launch_bounds__(256, 1)
void lstm_scan_persistent(const __half* __restrict__ WhT16,
                          const float* __restrict__ pxv,   // [V, 4H]
                          const int* __restrict__ xidx,    // [T, B]
                          const float* __restrict__ c_in,
                          __half* __restrict__ res,        // (T+1) slabs [B,H]
                          float* __restrict__ hf, float* __restrict__ cf)
{
    extern __shared__ __align__(16) char smem[];
    const uint32_t sb = smem_u32(smem);
    const int tid = threadIdx.x, lane = tid & 31, wid = tid >> 5;
    const int half = wid >> 2;                 // K-half: 0 or 1
    const int wq = wid & 3;                    // warp within quad
    const int u0 = blockIdx.x * 8;
    const int wm = (wq >> 1) * 16, wn = (wq & 1) * 32;

    // ---- load W_h slice into persistent SMEM (once; 256 threads) ----
    for (int idx = tid; idx < 4096; idx += 256) {
        int ck = idx >> 7, pos = idx & 127;
        int r = pos >> 2, seg = pos & 3;
        long grow = (long)(r >> 3) * H_SZ + u0 + (r & 7);   // gate*H + unit
        const __half* src = WhT16 + grow * H_SZ + ck * 32 + seg * 8;
        cp16(sb + (uint32_t)(ck * 2560 + r * 80 + seg * 16), src, 16u);
    }
    CP_COMMIT();

    // ---- c into registers: thread = (u in 0..7) x (2 batch rows) ----
    const int u = tid & 7;
    const int b0 = (tid >> 3) * 2;             // 0..62
    const int gu = u0 + u;
    float creg[2];
#pragma unroll
    for (int jj = 0; jj < 2; jj++) creg[jj] = c_in[(b0 + jj) * H_SZ + gu];

    // B-operand descriptors (per-quad: 128 threads cover a 64x80B stage)
    const int htid = tid & 127;
    uint32_t b_s[2];
    long b_row[2];
#pragma unroll
    for (int q = 0; q < 2; q++) {
        int pos = q * 128 + htid;
        int r = pos >> 2, c8 = (pos & 3) * 8;
        b_row[q] = (long)r * H_SZ + c8;
        b_s[q] = (uint32_t)(r * 80 + (pos & 3) * 16);
    }
    const uint32_t ringb = sb + A_BYTES + (uint32_t)half * RING_BYTES;
    // Gs0 in ring0 (quad0's ring), Gs1 in ring1 (quad1's ring): each quad
    // clobbers ONLY its own ring when writing gates -> quad-local sync is
    // enough before the write; one full sync before the cross-quad read.
    float* Gs0 = (float*)(smem + A_BYTES);
    float* Gs1 = (float*)(smem + A_BYTES + RING_BYTES);
    float* GsH = half ? Gs1 : Gs0;

    CP_WAIT0();
    __syncthreads();   // W_h slice ready

#define SB_LOAD(hhp, ck, s) do {                                              \
    const long ko = (long)(ck) * 32;                                          \
    const uint32_t st = ringb + (s) * SB_STG;                                 \
    _Pragma("unroll")                                                         \
    for (int q = 0; q < 2; q++)                                               \
        cp16(st + b_s[q], (hhp) + b_row[q] + ko, 16u);                        \
} while (0)

    const int ck0 = half * 16;                 // this quad's first K chunk

    for (int t = 0; t < T_STEPS; t++) {
        const __half* hh = res + (size_t)t * BH;
        __half*       oh = res + (size_t)(t + 1) * BH;

        // px gate prefetch via vocab gather (hidden behind the K-loop)
        float pr[2][4];
#pragma unroll
        for (int jj = 0; jj < 2; jj++) {
            const int row = xidx[t * B_SZ + b0 + jj];
            const float* pxb = pxv + (size_t)row * H4;
            pr[jj][0] = pxb[gu];
            pr[jj][1] = pxb[1024 + gu];
            pr[jj][2] = pxb[2048 + gu];
            pr[jj][3] = pxb[3072 + gu];
        }

        float acc[4][4];
#pragma unroll
        for (int j = 0; j < 4; j++)
#pragma unroll
            for (int q = 0; q < 4; q++) acc[j][q] = 0.f;

        SB_LOAD(hh, ck0 + 0, 0); CP_COMMIT();
        SB_LOAD(hh, ck0 + 1, 1); CP_COMMIT();
        SB_LOAD(hh, ck0 + 2, 2); CP_COMMIT();

        for (int i = 0; i < 16; i++) {
            const int s = i & 3;
            CP_WAIT2();
            BAR_SYNC(1 + half, 128);           // quad-local barrier
            const uint32_t sA = sb + (uint32_t)((ck0 + i) * 2560);
            const uint32_t sB = ringb + s * SB_STG;
#pragma unroll
            for (int ks = 0; ks < 2; ks++) {
                uint32_t ah[4], bh[8];
                const uint32_t ac = (uint32_t)(((lane >> 4) * 8 + ks * 16) * 2);
                ldsm4(ah, sA + (uint32_t)((wm + (lane & 15)) * 80) + ac);
                const int brow = (lane & 7) + ((lane >> 4) & 1) * 8;
                const uint32_t bcd = (uint32_t)(((((lane >> 3) & 1) * 8) + ks * 16) * 2);
#pragma unroll
                for (int pf = 0; pf < 2; pf++) {
                    uint32_t bd = sB + (uint32_t)((wn + pf * 16 + brow) * 80) + bcd;
                    ldsm4(&bh[pf * 4], bd);
                }
#pragma unroll
                for (int j = 0; j < 4; j++) {
                    const int bi = (j >> 1) * 4 + (j & 1) * 2;
                    mma_f16(acc[j], ah, bh[bi], bh[bi + 1]);
                }
            }
            if (i + 3 < 16) { SB_LOAD(hh, ck0 + i + 3, (i + 3) & 3); }
            CP_COMMIT();
        }

        // quad-local: all quad warps done reading own ring -> safe to write
        BAR_SYNC(1 + half, 128);
        {
            const int row = wm + (lane >> 2);
#pragma unroll
            for (int j = 0; j < 4; j++) {
                const int col = wn + j * 8 + (lane & 3) * 2;
                GsH[row * 65 + col]           = acc[j][0];
                GsH[row * 65 + col + 1]       = acc[j][1];
                GsH[(row + 8) * 65 + col]     = acc[j][2];
                GsH[(row + 8) * 65 + col + 1] = acc[j][3];
            }
        }
        __syncthreads();   // cross-quad: both Gs visible to all

#pragma unroll
        for (int jj = 0; jj < 2; jj++) {
            const int b = b0 + jj;
            float gi = Gs0[(0 * 8 + u) * 65 + b] + Gs1[(0 * 8 + u) * 65 + b] + pr[jj][0];
            float gf = Gs0[(1 * 8 + u) * 65 + b] + Gs1[(1 * 8 + u) * 65 + b] + pr[jj][1];
            float gg = Gs0[(2 * 8 + u) * 65 + b] + Gs1[(2 * 8 + u) * 65 + b] + pr[jj][2];
            float go = Gs0[(3 * 8 + u) * 65 + b] + Gs1[(3 * 8 + u) * 65 + b] + pr[jj][3];
            float si = fsig(gi);
            float sf = fsig(gf);
            float so = fsig(go);
            float tg = ftanh(gg);
            float cn = sf * creg[jj] + si * tg;
            float hn = so * ftanh(cn);
            creg[jj] = cn;
            const int ci = b * H_SZ + gu;
            oh[ci] = __float2half(hn);
            if (t == T_STEPS - 1) { hf[ci] = hn; cf[ci] = cn; }
        }

        // ---- grid barrier (R12 single-counter form — proven best) ----
        if (t < T_STEPS - 1) {
            __threadfence();
            __syncthreads();
            if (tid == 0) {
                atomicAdd(&g_bar, 1u);
                const unsigned target = (unsigned)SCAN_CTAS * (unsigned)(t + 1);
                while (atomicAdd(&g_bar, 0u) < target) { }
            }
            __syncthreads();
            __threadfence();
        }
    }
#undef SB_LOAD
}

// ===================== launch ================================================
extern "C" void kernel_launch(void* const* d_in, const int* in_sizes, int n_in,
                              void* d_out, int out_size)
{
    const int*   x      = (const int*)  d_in[0];
    const float* h      = (const float*)d_in[1];
    const float* c      = (const float*)d_in[2];
    const float* emb    = (const float*)d_in[3];
    const float* W_proj = (const float*)d_in[4];
    const float* b_proj = (const float*)d_in[5];
    const float* W_x    = (const float*)d_in[6];
    const float* W_h    = (const float*)d_in[7];
    const float* b_lstm = (const float*)d_in[8];
    const float* W_out  = (const float*)d_in[9];
    const float* b_out  = (const float*)d_in[10];
    float* out = (float*)d_out;

    float *pxv, *bc;
    unsigned int* bar;
    __nv_bfloat16 *wxth, *wxtl, *wph, *wpl;
    __half *r16h, *e16h, *wht16, *wot16, *wct16;
    cudaGetSymbolAddress((void**)&pxv,   g_px);
    cudaGetSymbolAddress((void**)&bc,    g_bc);
    cudaGetSymbolAddress((void**)&bar,   g_bar);
    cudaGetSymbolAddress((void**)&r16h,  g_res16h);
    cudaGetSymbolAddress((void**)&e16h,  g_emb16h);
    cudaGetSymbolAddress((void**)&wxth,  g_WxT_hi);
    cudaGetSymbolAddress((void**)&wxtl,  g_WxT_lo);
    cudaGetSymbolAddress((void**)&wht16, g_WhT16);
    cudaGetSymbolAddress((void**)&wot16, g_WoT16);
    cudaGetSymbolAddress((void**)&wph,   g_Wp_hi);
    cudaGetSymbolAddress((void**)&wpl,   g_Wp_lo);
    cudaGetSymbolAddress((void**)&wct16, g_WcT16);

    cudaFuncSetAttribute(mma_gemm_bf16,
                         cudaFuncAttributeMaxDynamicSharedMemorySize, G_SMEM_BYTES);
    cudaFuncSetAttribute(mma_gemm_f16,
                         cudaFuncAttributeMaxDynamicSharedMemorySize, 2 * 30720);
    cudaFuncSetAttribute(lstm_scan_persistent,
                         cudaFuncAttributeMaxDynamicSharedMemorySize, SCAN_SMEM);

    // ---------- prepass ----------
    cudaMemsetAsync(bar, 0, sizeof(unsigned int), 0);
    split_kernel<<<512, 256>>>(W_proj, wph, wpl, (long)H_SZ * H_SZ);
    conv16_kernel<<<2048, 256>>>(emb, e16h, (long)O_SZ * H_SZ);
    conv16_kernel<<<64, 256>>>(h, r16h, (long)BH);   // slab 0 = h_{-1}
    transpose_split_kernel<<<dim3(H4 / 32, H_SZ / 32), 256>>>(W_x, wxth, wxtl, H_SZ, H4);
    transpose16_kernel<<<dim3(H4 / 32, H_SZ / 32), 256>>>(W_h, wht16, H_SZ, H4);
    transpose16_kernel<<<dim3((O_SZ + 31) / 32, H_SZ / 32), 256>>>(W_out, wot16, H_SZ, O_SZ);
    bc_kernel<<<(H4 + 255) / 256, 256>>>(b_proj, W_x, b_lstm, bc);

    // ---------- Wc = (W_proj @ W_x)^T  (bf16x3, fp16 out) ----------
    mma_gemm_bf16<<<dim3(H_SZ / 128, H4 / 128), 256, G_SMEM_BYTES>>>(
        wxth, wxtl, wph, wpl, wct16, H4, H_SZ);

    // ---------- pxv = emb @ WcT^T + bc over the VOCABULARY  [V, 4H] ----------
    mma_gemm_f16<<<dim3(H4 / 256, (V_SZ + 127) / 128), 256, 2 * 30720>>>(
        e16h, wct16, bc, pxv, V_SZ, H4);

    // ---------- persistent LSTM scan (gathers pxv[x[t,b]]) ----------
    float* hf_out = out + (size_t)TB * O_SZ;
    float* cf_out = hf_out + BH;
    lstm_scan_persistent<<<SCAN_CTAS, 256, SCAN_SMEM>>>(
        wht16, pxv, x, c, r16h, hf_out, cf_out);

    // ---------- out = res @ W_out^T + b_out  (single launch) ----------
    mma_gemm_f16<<<dim3((O_SZ + 255) / 256, TB / 128), 256, 2 * 30720>>>(
        r16h + BH, wot16, b_out, out, TB, O_SZ);
}

// round 15
// speedup vs baseline: 1.4539x; 1.0338x over previous
#include <cuda_runtime.h>
#include <cuda_bf16.h>
#include <cuda_fp16.h>
#include <cstdint>
#include <math.h>

#define T_STEPS 256
#define B_SZ 64
#define H_SZ 1024
#define H4 4096
#define O_SZ 10000
#define V_SZ 10000
#define TB (T_STEPS * B_SZ)
#define BH (B_SZ * H_SZ)

// ===================== low-level helpers (sm_80+ features only) =============
__device__ __forceinline__ uint32_t smem_u32(const void* p) {
    uint32_t a;
    asm("{ .reg .u64 t; cvta.to.shared.u64 t, %1; cvt.u32.u64 %0, t; }"
        : "=r"(a) : "l"(p));
    return a;
}
__device__ __forceinline__ void ldsm4(uint32_t* r, uint32_t a) {
    asm volatile("ldmatrix.sync.aligned.m8n8.x4.shared.b16 {%0,%1,%2,%3}, [%4];"
                 : "=r"(r[0]), "=r"(r[1]), "=r"(r[2]), "=r"(r[3]) : "r"(a));
}
__device__ __forceinline__ void mma_bf16(float* c, const uint32_t* a,
                                         uint32_t b0, uint32_t b1) {
    asm volatile(
        "mma.sync.aligned.m16n8k16.row.col.f32.bf16.bf16.f32 "
        "{%0,%1,%2,%3}, {%4,%5,%6,%7}, {%8,%9}, {%0,%1,%2,%3};"
        : "+f"(c[0]), "+f"(c[1]), "+f"(c[2]), "+f"(c[3])
        : "r"(a[0]), "r"(a[1]), "r"(a[2]), "r"(a[3]), "r"(b0), "r"(b1));
}
__device__ __forceinline__ void mma_f16(float* c, const uint32_t* a,
                                        uint32_t b0, uint32_t b1) {
    asm volatile(
        "mma.sync.aligned.m16n8k16.row.col.f32.f16.f16.f32 "
        "{%0,%1,%2,%3}, {%4,%5,%6,%7}, {%8,%9}, {%0,%1,%2,%3};"
        : "+f"(c[0]), "+f"(c[1]), "+f"(c[2]), "+f"(c[3])
        : "r"(a[0]), "r"(a[1]), "r"(a[2]), "r"(a[3]), "r"(b0), "r"(b1));
}
__device__ __forceinline__ void cp16(uint32_t dst, const void* src, uint32_t sz) {
    asm volatile("cp.async.cg.shared.global [%0], [%1], 16, %2;"
                 :: "r"(dst), "l"(src), "r"(sz) : "memory");
}
#define CP_COMMIT() asm volatile("cp.async.commit_group;" ::: "memory")
#define CP_WAIT0()  asm volatile("cp.async.wait_group 0;" ::: "memory")
#define CP_WAIT1()  asm volatile("cp.async.wait_group 1;" ::: "memory")
#define CP_WAIT2()  asm volatile("cp.async.wait_group 2;" ::: "memory")
#define BAR_SYNC(id, n) asm volatile("bar.sync %0, %1;" :: "r"(id), "r"(n) : "memory")

__device__ __forceinline__ void split_bf(float x, __nv_bfloat16& hi, __nv_bfloat16& lo) {
    hi = __float2bfloat16(x);
    lo = __float2bfloat16(x - __bfloat162float(hi));
}
__device__ __forceinline__ float fsig(float x) {
    return __fdividef(1.f, 1.f + __expf(-x));
}
__device__ __forceinline__ float ftanh(float x) {
    return 1.f - __fdividef(2.f, __expf(2.f * x) + 1.f);
}

// ===================== scratch (device globals) ==============================
#define SCAN_CTAS 128
#define N_TILE_X 40
#define N_TILE_Y 128
__device__ float          g_px[(size_t)TB * H4];   // pxv[V(+pad), 4H]
__device__ float          g_bc[H4];
__device__ unsigned int   g_bar;
__device__ unsigned int   g_done[N_TILE_X * N_TILE_Y];
__device__ __half         g_res16h[(size_t)(T_STEPS + 1) * BH];
__device__ __half         g_emb16h[(size_t)O_SZ * H_SZ];
__device__ __nv_bfloat16  g_WxT_hi[(size_t)H4 * H_SZ],   g_WxT_lo[(size_t)H4 * H_SZ];
__device__ __half         g_WhT16[(size_t)H4 * H_SZ];
__device__ __half         g_WoT16[(size_t)O_SZ * H_SZ];
__device__ __nv_bfloat16  g_Wp_hi[(size_t)H_SZ * H_SZ],  g_Wp_lo[(size_t)H_SZ * H_SZ];
__device__ __half         g_WcT16[(size_t)H4 * H_SZ];

// ===================== static streams/events =================================
static cudaStream_t g_s1;
static cudaEvent_t  g_evPx, g_evOv;
namespace {
struct StreamInit {
    StreamInit() {
        cudaStreamCreateWithFlags(&g_s1, cudaStreamNonBlocking);
        cudaEventCreateWithFlags(&g_evPx, cudaEventDisableTiming);
        cudaEventCreateWithFlags(&g_evOv, cudaEventDisableTiming);
    }
};
StreamInit g_streamInit;
}

// ===================== pre-pass kernels ======================================
__global__ void split_kernel(const float* __restrict__ in,
                             __nv_bfloat16* __restrict__ hi,
                             __nv_bfloat16* __restrict__ lo, long n) {
    long i = (long)blockIdx.x * blockDim.x + threadIdx.x;
    long stride = (long)gridDim.x * blockDim.x;
    for (; i < n; i += stride) split_bf(in[i], hi[i], lo[i]);
}
__global__ void conv16_kernel(const float* __restrict__ in,
                              __half* __restrict__ o, long n) {
    long i = (long)blockIdx.x * blockDim.x + threadIdx.x;
    long stride = (long)gridDim.x * blockDim.x;
    for (; i < n; i += stride) o[i] = __float2half(in[i]);
}
__global__ void transpose_split_kernel(const float* __restrict__ in,
                                       __nv_bfloat16* __restrict__ hiT,
                                       __nv_bfloat16* __restrict__ loT,
                                       int R, int C) {
    __shared__ float ts[32][33];
    int c0 = blockIdx.x * 32, r0 = blockIdx.y * 32;
    int tx = threadIdx.x & 31, ty = threadIdx.x >> 5;
    for (int rr = ty; rr < 32; rr += 8) {
        int r = r0 + rr, c = c0 + tx;
        ts[rr][tx] = (r < R && c < C) ? in[(size_t)r * C + c] : 0.f;
    }
    __syncthreads();
    for (int cc = ty; cc < 32; cc += 8) {
        int c = c0 + cc, r = r0 + tx;
        if (c < C && r < R) {
            __nv_bfloat16 h, l;
            split_bf(ts[tx][cc], h, l);
            hiT[(size_t)c * R + r] = h;
            loT[(size_t)c * R + r] = l;
        }
    }
}
__global__ void transpose16_kernel(const float* __restrict__ in,
                                   __half* __restrict__ hiT, int R, int C) {
    __shared__ float ts[32][33];
    int c0 = blockIdx.x * 32, r0 = blockIdx.y * 32;
    int tx = threadIdx.x & 31, ty = threadIdx.x >> 5;
    for (int rr = ty; rr < 32; rr += 8) {
        int r = r0 + rr, c = c0 + tx;
        ts[rr][tx] = (r < R && c < C) ? in[(size_t)r * C + c] : 0.f;
    }
    __syncthreads();
    for (int cc = ty; cc < 32; cc += 8) {
        int c = c0 + cc, r = r0 + tx;
        if (c < C && r < R) hiT[(size_t)c * R + r] = __float2half(ts[tx][cc]);
    }
}
__global__ void bc_kernel(const float* __restrict__ b_proj,
                          const float* __restrict__ W_x,
                          const float* __restrict__ b_lstm,
                          float* __restrict__ bc) {
    int n = blockIdx.x * blockDim.x + threadIdx.x;
    if (n >= H4) return;
    float s = b_lstm[n];
    for (int k = 0; k < H_SZ; k++) s += b_proj[k] * W_x[(size_t)k * H4 + n];
    bc[n] = s;
}
// tiny delay: wait until all scan CTAs are resident (g_bar >= 128) or timeout
__global__ void wait_scan_started() {
    long long s0 = clock64();
    while (*((volatile unsigned*)&g_bar) < (unsigned)SCAN_CTAS &&
           clock64() - s0 < 2000000LL)
        __nanosleep(512);
}

// ===================== bf16x3 GEMM (128x128) — Wc only ======================
#define G_SMEM_BYTES (2 * 40960)
__global__ __launch_bounds__(256, 1)
void mma_gemm_bf16(const __nv_bfloat16* __restrict__ Ah, const __nv_bfloat16* __restrict__ Al,
                   const __nv_bfloat16* __restrict__ Bh, const __nv_bfloat16* __restrict__ Bl,
                   __half* __restrict__ C16, int M, int N)
{
    extern __shared__ __align__(16) char smem[];
    const uint32_t sb = smem_u32(smem);
    const int tid = threadIdx.x, lane = tid & 31, wid = tid >> 5;
    const int bm = blockIdx.y * 128, bn = blockIdx.x * 128;
    const int wm = (wid >> 2) * 64, wn = (wid & 3) * 32;

    long a_off[2], b_off[2];
    uint32_t a_s[2], b_s[2], b_sz[2];
#pragma unroll
    for (int q = 0; q < 2; q++) {
        int pos = q * 256 + tid;
        int r = pos >> 2, c8 = (pos & 3) * 8;
        a_off[q] = (long)(bm + r) * H_SZ + c8;
        a_s[q] = (uint32_t)(r * 80 + (pos & 3) * 16);
        int gn = bn + r;
        b_sz[q]  = (gn < N) ? 16u : 0u;
        b_off[q] = (long)((gn < N) ? gn : 0) * H_SZ + c8;
        b_s[q] = a_s[q];
    }

    float acc[4][4][4];
#pragma unroll
    for (int m = 0; m < 4; m++)
#pragma unroll
        for (int j = 0; j < 4; j++)
#pragma unroll
            for (int q = 0; q < 4; q++) acc[m][j][q] = 0.f;

#define GB_LOAD(ck, s) do {                                                   \
    const long ko = (long)(ck) * 32;                                          \
    const uint32_t st = sb + (s) * 40960;                                     \
    _Pragma("unroll")                                                         \
    for (int q = 0; q < 2; q++) {                                             \
        cp16(st + a_s[q],         Ah + a_off[q] + ko, 16u);                   \
        cp16(st + 10240 + a_s[q], Al + a_off[q] + ko, 16u);                   \
        cp16(st + 20480 + b_s[q], Bh + b_off[q] + ko, b_sz[q]);               \
        cp16(st + 30720 + b_s[q], Bl + b_off[q] + ko, b_sz[q]);               \
    }                                                                         \
} while (0)

    GB_LOAD(0, 0); CP_COMMIT();
    GB_LOAD(1, 1); CP_COMMIT();

    for (int ck = 0; ck < 32; ck++) {
        const int s = ck & 1;
        CP_WAIT1();
        __syncthreads();
        const uint32_t sA = sb + s * 40960;
        const uint32_t sB = sA + 20480;
#pragma unroll
        for (int ks = 0; ks < 2; ks++) {
            uint32_t ah[4][4], al[4][4], bh[8], bl[8];
            const int arow = lane & 15;
            const uint32_t ac = (uint32_t)(((lane >> 4) * 8 + ks * 16) * 2);
#pragma unroll
            for (int mf = 0; mf < 4; mf++) {
                uint32_t ad = sA + (uint32_t)((wm + mf * 16 + arow) * 80) + ac;
                ldsm4(ah[mf], ad);
                ldsm4(al[mf], ad + 10240);
            }
            const int brow = (lane & 7) + ((lane >> 4) & 1) * 8;
            const uint32_t bcd = (uint32_t)(((((lane >> 3) & 1) * 8) + ks * 16) * 2);
#pragma unroll
            for (int pf = 0; pf < 2; pf++) {
                uint32_t bd = sB + (uint32_t)((wn + pf * 16 + brow) * 80) + bcd;
                ldsm4(&bh[pf * 4], bd);
                ldsm4(&bl[pf * 4], bd + 10240);
            }
#pragma unroll
            for (int m = 0; m < 4; m++)
#pragma unroll
                for (int j = 0; j < 4; j++) {
                    const int bi = (j >> 1) * 4 + (j & 1) * 2;
                    mma_bf16(acc[m][j], ah[m], bh[bi], bh[bi + 1]);
                    mma_bf16(acc[m][j], al[m], bh[bi], bh[bi + 1]);
                    mma_bf16(acc[m][j], ah[m], bl[bi], bl[bi + 1]);
                }
        }
        __syncthreads();
        if (ck + 2 < 32) GB_LOAD(ck + 2, s);
        CP_COMMIT();
    }

#pragma unroll
    for (int m = 0; m < 4; m++) {
        const int r0 = bm + wm + m * 16 + (lane >> 2);
#pragma unroll
        for (int j = 0; j < 4; j++) {
            const int col = bn + wn + j * 8 + (lane & 3) * 2;
#pragma unroll
            for (int hh = 0; hh < 2; hh++) {
                const int r = r0 + hh * 8;
                if (col < N)     C16[(size_t)r * N + col]     = __float2half(acc[m][j][hh * 2 + 0]);
                if (col + 1 < N) C16[(size_t)r * N + col + 1] = __float2half(acc[m][j][hh * 2 + 1]);
            }
        }
    }
#undef GB_LOAD
}

// ===================== fp16 GEMM (128x256), single A-pass, 2-stage ==========
// MODE 0: plain. MODE 1: overlap (wait on scan progress, mark done tiles,
// give up on stall). MODE 2: fixup (skip tiles already done).
template <int MODE>
__global__ __launch_bounds__(256, 1)
void mma_gemm_f16(const __half* __restrict__ Ah,
                  const __half* __restrict__ Bh,
                  const float* __restrict__ bias,
                  float* __restrict__ C, int M, int N)
{
    extern __shared__ __align__(16) char smem[];
    const uint32_t sb = smem_u32(smem);
    const int tid = threadIdx.x, lane = tid & 31, wid = tid >> 5;

    const int tileId = blockIdx.y * gridDim.x + blockIdx.x;
    if (MODE == 2) {
        if (g_done[tileId]) return;     // computed by overlap kernel
    }
    if (MODE == 1) {
        __shared__ int s_go;
        if (tid == 0) {
            const int k = blockIdx.y >> 3;                  // M-chunk (1024 rows)
            const unsigned needed = 2048u * (unsigned)(k + 1);
            volatile unsigned* prog = (volatile unsigned*)&g_bar;
            unsigned cur = *prog;
            long long lastChg = clock64();
            int go = 1;
            while (cur < needed) {
                __nanosleep(256);
                unsigned now = *prog;
                if (now != cur) { cur = now; lastChg = clock64(); }
                else if (clock64() - lastChg > 150000LL) { go = 0; break; }
            }
            s_go = go;
        }
        __syncthreads();
        if (!s_go) return;              // leave tile for fixup pass
        __threadfence();                // acquire: order data loads after flag
    }

    const int bm = blockIdx.y * 128, bn = blockIdx.x * 256;
    const int wm = (wid >> 2) * 64, wn = (wid & 3) * 64;

    long a_off[2];
    uint32_t a_s[2];
#pragma unroll
    for (int q = 0; q < 2; q++) {
        int pos = q * 256 + tid;
        int r = pos >> 2, c8 = (pos & 3) * 8;
        int ar = bm + r; if (ar >= M) ar = M - 1;       // M-clamp
        a_off[q] = (long)ar * H_SZ + c8;
        a_s[q] = (uint32_t)(r * 80 + (pos & 3) * 16);
    }
    long b_off[4];
    uint32_t b_s[4], b_sz[4];
#pragma unroll
    for (int q = 0; q < 4; q++) {
        int pos = q * 256 + tid;
        int r = pos >> 2, c8 = (pos & 3) * 8;
        int gn = bn + r;
        b_sz[q]  = (gn < N) ? 16u : 0u;
        b_off[q] = (long)((gn < N) ? gn : 0) * H_SZ + c8;
        b_s[q] = (uint32_t)(r * 80 + (pos & 3) * 16);
    }

    float acc[4][8][4];
#pragma unroll
    for (int m = 0; m < 4; m++)
#pragma unroll
        for (int j = 0; j < 8; j++)
#pragma unroll
            for (int q = 0; q < 4; q++) acc[m][j][q] = 0.f;

#define G2_LOAD(ck, s) do {                                                   \
    const long ko = (long)(ck) * 32;                                          \
    const uint32_t st = sb + (s) * 30720;                                     \
    _Pragma("unroll")                                                         \
    for (int q = 0; q < 2; q++)                                               \
        cp16(st + a_s[q], Ah + a_off[q] + ko, 16u);                           \
    _Pragma("unroll")                                                         \
    for (int q = 0; q < 4; q++)                                               \
        cp16(st + 10240 + b_s[q], Bh + b_off[q] + ko, b_sz[q]);               \
} while (0)

    G2_LOAD(0, 0); CP_COMMIT();
    G2_LOAD(1, 1); CP_COMMIT();

    for (int ck = 0; ck < 32; ck++) {
        const int s = ck & 1;
        CP_WAIT1();
        __syncthreads();
        const uint32_t sA = sb + s * 30720;
        const uint32_t sB = sA + 10240;
#pragma unroll
        for (int ks = 0; ks < 2; ks++) {
            uint32_t ah[4][4], bh[16];
            const int arow = lane & 15;
            const uint32_t ac = (uint32_t)(((lane >> 4) * 8 + ks * 16) * 2);
#pragma unroll
            for (int mf = 0; mf < 4; mf++) {
                uint32_t ad = sA + (uint32_t)((wm + mf * 16 + arow) * 80) + ac;
                ldsm4(ah[mf], ad);
            }
            const int brow = (lane & 7) + ((lane >> 4) & 1) * 8;
            const uint32_t bcd = (uint32_t)(((((lane >> 3) & 1) * 8) + ks * 16) * 2);
#pragma unroll
            for (int pf = 0; pf < 4; pf++) {
                uint32_t bd = sB + (uint32_t)((wn + pf * 16 + brow) * 80) + bcd;
                ldsm4(&bh[pf * 4], bd);
            }
#pragma unroll
            for (int m = 0; m < 4; m++)
#pragma unroll
                for (int j = 0; j < 8; j++) {
                    const int bi = (j >> 1) * 4 + (j & 1) * 2;
                    mma_f16(acc[m][j], ah[m], bh[bi], bh[bi + 1]);
                }
        }
        __syncthreads();
        if (ck + 2 < 32) G2_LOAD(ck + 2, s);
        CP_COMMIT();
    }

#pragma unroll
    for (int m = 0; m < 4; m++) {
        const int r0 = bm + wm + m * 16 + (lane >> 2);
#pragma unroll
        for (int j = 0; j < 8; j++) {
            const int col = bn + wn + j * 8 + (lane & 3) * 2;
#pragma unroll
            for (int hh = 0; hh < 2; hh++) {
                const int r = r0 + hh * 8;
                if (col < N)     C[(size_t)r * N + col]     = acc[m][j][hh * 2 + 0] + bias[col];
                if (col + 1 < N) C[(size_t)r * N + col + 1] = acc[m][j][hh * 2 + 1] + bias[col + 1];
            }
        }
    }
    if (MODE == 1) {
        __syncthreads();
        if (tid == 0) g_done[tileId] = 1u;   // read only after kernel completes
    }
#undef G2_LOAD
}

// ===================== persistent LSTM scan (8 warps, K-split) ==============
#define A_BYTES   (32 * 2560)
#define SB_STG    5120
#define RING_BYTES (4 * SB_STG)
#define SCAN_SMEM (A_BYTES + 2 * RING_BYTES)   // 122880 B

__global__ __launch_bounds__(256, 1)
void lstm_scan_persistent(const __half* __restrict__ WhT16,
                          const float* __restrict__ pxv,   // [V, 4H]
                          const int* __restrict__ xidx,    // [T, B]
                          const float* __restrict__ c_in,
                          __half* __restrict__ res,        // (T+1) slabs [B,H]
                          float* __restrict__ hf, float* __restrict__ cf)
{
    extern __shared__ __align__(16) char smem[];
    const uint32_t sb = smem_u32(smem);
    const int tid = threadIdx.x, lane = tid & 31, wid = tid >> 5;
    const int half = wid >> 2;
    const int wq = wid & 3;
    const int u0 = blockIdx.x * 8;
    const int wm = (wq >> 1) * 16, wn = (wq & 1) * 32;

    for (int idx = tid; idx < 4096; idx += 256) {
        int ck = idx >> 7, pos = idx & 127;
        int r = pos >> 2, seg = pos & 3;
        long grow = (long)(r >> 3) * H_SZ + u0 + (r & 7);
        const __half* src = WhT16 + grow * H_SZ + ck * 32 + seg * 8;
        cp16(sb + (uint32_t)(ck * 2560 + r * 80 + seg * 16), src, 16u);
    }
    CP_COMMIT();

    const int u = tid & 7;
    const int b0 = (tid >> 3) * 2;
    const int gu = u0 + u;
    float creg[2];
#pragma unroll
    for (int jj = 0; jj < 2; jj++) creg[jj] = c_in[(b0 + jj) * H_SZ + gu];

    const int htid = tid & 127;
    uint32_t b_s[2];
    long b_row[2];
#pragma unroll
    for (int q = 0; q < 2; q++) {
        int pos = q * 128 + htid;
        int r = pos >> 2, c8 = (pos & 3) * 8;
        b_row[q] = (long)r * H_SZ + c8;
        b_s[q] = (uint32_t)(r * 80 + (pos & 3) * 16);
    }
    const uint32_t ringb = sb + A_BYTES + (uint32_t)half * RING_BYTES;
    float* Gs0 = (float*)(smem + A_BYTES);
    float* Gs1 = (float*)(smem + A_BYTES + RING_BYTES);
    float* GsH = half ? Gs1 : Gs0;

    CP_WAIT0();
    __syncthreads();

#define SB_LOAD(hhp, ck, s) do {                                              \
    const long ko = (long)(ck) * 32;                                          \
    const uint32_t st = ringb + (s) * SB_STG;                                 \
    _Pragma("unroll")                                                         \
    for (int q = 0; q < 2; q++)                                               \
        cp16(st + b_s[q], (hhp) + b_row[q] + ko, 16u);                        \
} while (0)

    const int ck0 = half * 16;

    for (int t = 0; t < T_STEPS; t++) {
        const __half* hh = res + (size_t)t * BH;
        __half*       oh = res + (size_t)(t + 1) * BH;

        float pr[2][4];
#pragma unroll
        for (int jj = 0; jj < 2; jj++) {
            const int row = xidx[t * B_SZ + b0 + jj];
            const float* pxb = pxv + (size_t)row * H4;
            pr[jj][0] = pxb[gu];
            pr[jj][1] = pxb[1024 + gu];
            pr[jj][2] = pxb[2048 + gu];
            pr[jj][3] = pxb[3072 + gu];
        }

        float acc[4][4];
#pragma unroll
        for (int j = 0; j < 4; j++)
#pragma unroll
            for (int q = 0; q < 4; q++) acc[j][q] = 0.f;

        SB_LOAD(hh, ck0 + 0, 0); CP_COMMIT();
        SB_LOAD(hh, ck0 + 1, 1); CP_COMMIT();
        SB_LOAD(hh, ck0 + 2, 2); CP_COMMIT();

        for (int i = 0; i < 16; i++) {
            const int s = i & 3;
            CP_WAIT2();
            BAR_SYNC(1 + half, 128);
            const uint32_t sA = sb + (uint32_t)((ck0 + i) * 2560);
            const uint32_t sB = ringb + s * SB_STG;
#pragma unroll
            for (int ks = 0; ks < 2; ks++) {
                uint32_t ah[4], bh[8];
                const uint32_t ac = (uint32_t)(((lane >> 4) * 8 + ks * 16) * 2);
                ldsm4(ah, sA + (uint32_t)((wm + (lane & 15)) * 80) + ac);
                const int brow = (lane & 7) + ((lane >> 4) & 1) * 8;
                const uint32_t bcd = (uint32_t)(((((lane >> 3) & 1) * 8) + ks * 16) * 2);
#pragma unroll
                for (int pf = 0; pf < 2; pf++) {
                    uint32_t bd = sB + (uint32_t)((wn + pf * 16 + brow) * 80) + bcd;
                    ldsm4(&bh[pf * 4], bd);
                }
#pragma unroll
                for (int j = 0; j < 4; j++) {
                    const int bi = (j >> 1) * 4 + (j & 1) * 2;
                    mma_f16(acc[j], ah, bh[bi], bh[bi + 1]);
                }
            }
            if (i + 3 < 16) { SB_LOAD(hh, ck0 + i + 3, (i + 3) & 3); }
            CP_COMMIT();
        }

        BAR_SYNC(1 + half, 128);
        {
            const int row = wm + (lane >> 2);
#pragma unroll
            for (int j = 0; j < 4; j++) {
                const int col = wn + j * 8 + (lane & 3) * 2;
                GsH[row * 65 + col]           = acc[j][0];
                GsH[row * 65 + col + 1]       = acc[j][1];
                GsH[(row + 8) * 65 + col]     = acc[j][2];
                GsH[(row + 8) * 65 + col + 1] = acc[j][3];
            }
        }
        __syncthreads();

#pragma unroll
        for (int jj = 0; jj < 2; jj++) {
            const int b = b0 + jj;
            float gi = Gs0[(0 * 8 + u) * 65 + b] + Gs1[(0 * 8 + u) * 65 + b] + pr[jj][0];
            float gf = Gs0[(1 * 8 + u) * 65 + b] + Gs1[(1 * 8 + u) * 65 + b] + pr[jj][1];
            float gg = Gs0[(2 * 8 + u) * 65 + b] + Gs1[(2 * 8 + u) * 65 + b] + pr[jj][2];
            float go = Gs0[(3 * 8 + u) * 65 + b] + Gs1[(3 * 8 + u) * 65 + b] + pr[jj][3];
            float si = fsig(gi);
            float sf = fsig(gf);
            float so = fsig(go);
            float tg = ftanh(gg);
            float cn = sf * creg[jj] + si * tg;
            float hn = so * ftanh(cn);
            creg[jj] = cn;
            const int ci = b * H_SZ + gu;
            oh[ci] = __float2half(hn);
            if (t == T_STEPS - 1) { hf[ci] = hn; cf[ci] = cn; }
        }

        // ---- grid barrier: arrive EVERY step (progress ticker); wait except last
        __threadfence();
        __syncthreads();
        if (tid == 0) {
            atomicAdd(&g_bar, 1u);
            if (t < T_STEPS - 1) {
                const unsigned target = (unsigned)SCAN_CTAS * (unsigned)(t + 1);
                while (atomicAdd(&g_bar, 0u) < target) { }
            }
        }
        __syncthreads();
        __threadfence();
    }
#undef SB_LOAD
}

// ===================== launch ================================================
extern "C" void kernel_launch(void* const* d_in, const int* in_sizes, int n_in,
                              void* d_out, int out_size)
{
    const int*   x      = (const int*)  d_in[0];
    const float* h      = (const float*)d_in[1];
    const float* c      = (const float*)d_in[2];
    const float* emb    = (const float*)d_in[3];
    const float* W_proj = (const float*)d_in[4];
    const float* b_proj = (const float*)d_in[5];
    const float* W_x    = (const float*)d_in[6];
    const float* W_h    = (const float*)d_in[7];
    const float* b_lstm = (const float*)d_in[8];
    const float* W_out  = (const float*)d_in[9];
    const float* b_out  = (const float*)d_in[10];
    float* out = (float*)d_out;

    float *pxv, *bc;
    unsigned int *bar, *done;
    __nv_bfloat16 *wxth, *wxtl, *wph, *wpl;
    __half *r16h, *e16h, *wht16, *wot16, *wct16;
    cudaGetSymbolAddress((void**)&pxv,   g_px);
    cudaGetSymbolAddress((void**)&bc,    g_bc);
    cudaGetSymbolAddress((void**)&bar,   g_bar);
    cudaGetSymbolAddress((void**)&done,  g_done);
    cudaGetSymbolAddress((void**)&r16h,  g_res16h);
    cudaGetSymbolAddress((void**)&e16h,  g_emb16h);
    cudaGetSymbolAddress((void**)&wxth,  g_WxT_hi);
    cudaGetSymbolAddress((void**)&wxtl,  g_WxT_lo);
    cudaGetSymbolAddress((void**)&wht16, g_WhT16);
    cudaGetSymbolAddress((void**)&wot16, g_WoT16);
    cudaGetSymbolAddress((void**)&wph,   g_Wp_hi);
    cudaGetSymbolAddress((void**)&wpl,   g_Wp_lo);
    cudaGetSymbolAddress((void**)&wct16, g_WcT16);

    cudaFuncSetAttribute(mma_gemm_bf16,
                         cudaFuncAttributeMaxDynamicSharedMemorySize, G_SMEM_BYTES);
    cudaFuncSetAttribute(mma_gemm_f16<0>,
                         cudaFuncAttributeMaxDynamicSharedMemorySize, 2 * 30720);
    cudaFuncSetAttribute(mma_gemm_f16<1>,
                         cudaFuncAttributeMaxDynamicSharedMemorySize, 2 * 30720);
    cudaFuncSetAttribute(mma_gemm_f16<2>,
                         cudaFuncAttributeMaxDynamicSharedMemorySize, 2 * 30720);
    cudaFuncSetAttribute(lstm_scan_persistent,
                         cudaFuncAttributeMaxDynamicSharedMemorySize, SCAN_SMEM);

    // ---------- prepass (stream 0) ----------
    cudaMemsetAsync(bar, 0, sizeof(unsigned int), 0);
    cudaMemsetAsync(done, 0, N_TILE_X * N_TILE_Y * sizeof(unsigned int), 0);
    split_kernel<<<512, 256>>>(W_proj, wph, wpl, (long)H_SZ * H_SZ);
    conv16_kernel<<<2048, 256>>>(emb, e16h, (long)O_SZ * H_SZ);
    conv16_kernel<<<64, 256>>>(h, r16h, (long)BH);   // slab 0 = h_{-1}
    transpose_split_kernel<<<dim3(H4 / 32, H_SZ / 32), 256>>>(W_x, wxth, wxtl, H_SZ, H4);
    transpose16_kernel<<<dim3(H4 / 32, H_SZ / 32), 256>>>(W_h, wht16, H_SZ, H4);
    transpose16_kernel<<<dim3((O_SZ + 31) / 32, H_SZ / 32), 256>>>(W_out, wot16, H_SZ, O_SZ);
    bc_kernel<<<(H4 + 255) / 256, 256>>>(b_proj, W_x, b_lstm, bc);

    // ---------- Wc, then pxv (stream 0) ----------
    mma_gemm_bf16<<<dim3(H_SZ / 128, H4 / 128), 256, G_SMEM_BYTES>>>(
        wxth, wxtl, wph, wpl, wct16, H4, H_SZ);
    mma_gemm_f16<0><<<dim3(H4 / 256, (V_SZ + 127) / 128), 256, 2 * 30720>>>(
        e16h, wct16, bc, pxv, V_SZ, H4);
    cudaEventRecord(g_evPx, 0);

    // ---------- persistent scan (stream 0) ----------
    float* hf_out = out + (size_t)TB * O_SZ;
    float* cf_out = hf_out + BH;
    lstm_scan_persistent<<<SCAN_CTAS, 256, SCAN_SMEM>>>(
        wht16, pxv, x, c, r16h, hf_out, cf_out);

    // ---------- overlapped out GEMM on s1 (after scan is resident) ----------
    cudaStreamWaitEvent(g_s1, g_evPx, 0);
    wait_scan_started<<<1, 1, 0, g_s1>>>();
    mma_gemm_f16<1><<<dim3(N_TILE_X, N_TILE_Y), 256, 2 * 30720, g_s1>>>(
        r16h + BH, wot16, b_out, out, TB, O_SZ);
    cudaEventRecord(g_evOv, g_s1);

    // ---------- fixup pass (stream 0, after scan AND overlap) ----------
    cudaStreamWaitEvent(0, g_evOv, 0);
    mma_gemm_f16<2><<<dim3(N_TILE_X, N_TILE_Y), 256, 2 * 30720>>>(
        r16h + BH, wot16, b_out, out, TB, O_SZ);
}

// round 16
// speedup vs baseline: 1.4555x; 1.0011x over previous
#include <cuda_runtime.h>
#include <cuda_bf16.h>
#include <cuda_fp16.h>
#include <cstdint>
#include <math.h>

#define T_STEPS 256
#define B_SZ 64
#define H_SZ 1024
#define H4 4096
#define O_SZ 10000
#define V_SZ 10000
#define TB (T_STEPS * B_SZ)
#define BH (B_SZ * H_SZ)

// ===================== low-level helpers (sm_80+ features only) =============
__device__ __forceinline__ uint32_t smem_u32(const void* p) {
    uint32_t a;
    asm("{ .reg .u64 t; cvta.to.shared.u64 t, %1; cvt.u32.u64 %0, t; }"
        : "=r"(a) : "l"(p));
    return a;
}
__device__ __forceinline__ void ldsm4(uint32_t* r, uint32_t a) {
    asm volatile("ldmatrix.sync.aligned.m8n8.x4.shared.b16 {%0,%1,%2,%3}, [%4];"
                 : "=r"(r[0]), "=r"(r[1]), "=r"(r[2]), "=r"(r[3]) : "r"(a));
}
__device__ __forceinline__ void mma_bf16(float* c, const uint32_t* a,
                                         uint32_t b0, uint32_t b1) {
    asm volatile(
        "mma.sync.aligned.m16n8k16.row.col.f32.bf16.bf16.f32 "
        "{%0,%1,%2,%3}, {%4,%5,%6,%7}, {%8,%9}, {%0,%1,%2,%3};"
        : "+f"(c[0]), "+f"(c[1]), "+f"(c[2]), "+f"(c[3])
        : "r"(a[0]), "r"(a[1]), "r"(a[2]), "r"(a[3]), "r"(b0), "r"(b1));
}
__device__ __forceinline__ void mma_f16(float* c, const uint32_t* a,
                                        uint32_t b0, uint32_t b1) {
    asm volatile(
        "mma.sync.aligned.m16n8k16.row.col.f32.f16.f16.f32 "
        "{%0,%1,%2,%3}, {%4,%5,%6,%7}, {%8,%9}, {%0,%1,%2,%3};"
        : "+f"(c[0]), "+f"(c[1]), "+f"(c[2]), "+f"(c[3])
        : "r"(a[0]), "r"(a[1]), "r"(a[2]), "r"(a[3]), "r"(b0), "r"(b1));
}
__device__ __forceinline__ void cp16(uint32_t dst, const void* src, uint32_t sz) {
    asm volatile("cp.async.cg.shared.global [%0], [%1], 16, %2;"
                 :: "r"(dst), "l"(src), "r"(sz) : "memory");
}
#define CP_COMMIT() asm volatile("cp.async.commit_group;" ::: "memory")
#define CP_WAIT0()  asm volatile("cp.async.wait_group 0;" ::: "memory")
#define CP_WAIT1()  asm volatile("cp.async.wait_group 1;" ::: "memory")
#define CP_WAIT2()  asm volatile("cp.async.wait_group 2;" ::: "memory")
#define BAR_SYNC(id, n) asm volatile("bar.sync %0, %1;" :: "r"(id), "r"(n) : "memory")

__device__ __forceinline__ void split_bf(float x, __nv_bfloat16& hi, __nv_bfloat16& lo) {
    hi = __float2bfloat16(x);
    lo = __float2bfloat16(x - __bfloat162float(hi));
}
__device__ __forceinline__ float fsig(float x) {
    return __fdividef(1.f, 1.f + __expf(-x));
}
__device__ __forceinline__ float ftanh(float x) {
    return 1.f - __fdividef(2.f, __expf(2.f * x) + 1.f);
}

// ===================== scratch (device globals) ==============================
#define SCAN_CTAS 128
#define OT_X 79                       // ceil(10000/128)
#define OT_Y 128                      // 16384/128
__device__ float          g_px[(size_t)TB * H4];   // pxv[V(+pad), 4H]
__device__ float          g_bc[H4];
__device__ unsigned int   g_bar;
__device__ unsigned int   g_done[OT_X * OT_Y];
__device__ __half         g_res16h[(size_t)(T_STEPS + 1) * BH];
__device__ __half         g_emb16h[(size_t)O_SZ * H_SZ];
__device__ __nv_bfloat16  g_WxT_hi[(size_t)H4 * H_SZ],   g_WxT_lo[(size_t)H4 * H_SZ];
__device__ __half         g_WhT16[(size_t)H4 * H_SZ];
__device__ __half         g_WoT16[(size_t)O_SZ * H_SZ];
__device__ __nv_bfloat16  g_Wp_hi[(size_t)H_SZ * H_SZ],  g_Wp_lo[(size_t)H_SZ * H_SZ];
__device__ __half         g_WcT16[(size_t)H4 * H_SZ];

// ===================== static streams/events =================================
static cudaStream_t g_s1;
static cudaEvent_t  g_evPx, g_evOv;
namespace {
struct StreamInit {
    StreamInit() {
        cudaStreamCreateWithFlags(&g_s1, cudaStreamNonBlocking);
        cudaEventCreateWithFlags(&g_evPx, cudaEventDisableTiming);
        cudaEventCreateWithFlags(&g_evOv, cudaEventDisableTiming);
    }
};
StreamInit g_streamInit;
}

// ===================== pre-pass kernels ======================================
__global__ void split_kernel(const float* __restrict__ in,
                             __nv_bfloat16* __restrict__ hi,
                             __nv_bfloat16* __restrict__ lo, long n) {
    long i = (long)blockIdx.x * blockDim.x + threadIdx.x;
    long stride = (long)gridDim.x * blockDim.x;
    for (; i < n; i += stride) split_bf(in[i], hi[i], lo[i]);
}
__global__ void conv16_kernel(const float* __restrict__ in,
                              __half* __restrict__ o, long n) {
    long i = (long)blockIdx.x * blockDim.x + threadIdx.x;
    long stride = (long)gridDim.x * blockDim.x;
    for (; i < n; i += stride) o[i] = __float2half(in[i]);
}
__global__ void transpose_split_kernel(const float* __restrict__ in,
                                       __nv_bfloat16* __restrict__ hiT,
                                       __nv_bfloat16* __restrict__ loT,
                                       int R, int C) {
    __shared__ float ts[32][33];
    int c0 = blockIdx.x * 32, r0 = blockIdx.y * 32;
    int tx = threadIdx.x & 31, ty = threadIdx.x >> 5;
    for (int rr = ty; rr < 32; rr += 8) {
        int r = r0 + rr, c = c0 + tx;
        ts[rr][tx] = (r < R && c < C) ? in[(size_t)r * C + c] : 0.f;
    }
    __syncthreads();
    for (int cc = ty; cc < 32; cc += 8) {
        int c = c0 + cc, r = r0 + tx;
        if (c < C && r < R) {
            __nv_bfloat16 h, l;
            split_bf(ts[tx][cc], h, l);
            hiT[(size_t)c * R + r] = h;
            loT[(size_t)c * R + r] = l;
        }
    }
}
__global__ void transpose16_kernel(const float* __restrict__ in,
                                   __half* __restrict__ hiT, int R, int C) {
    __shared__ float ts[32][33];
    int c0 = blockIdx.x * 32, r0 = blockIdx.y * 32;
    int tx = threadIdx.x & 31, ty = threadIdx.x >> 5;
    for (int rr = ty; rr < 32; rr += 8) {
        int r = r0 + rr, c = c0 + tx;
        ts[rr][tx] = (r < R && c < C) ? in[(size_t)r * C + c] : 0.f;
    }
    __syncthreads();
    for (int cc = ty; cc < 32; cc += 8) {
        int c = c0 + cc, r = r0 + tx;
        if (c < C && r < R) hiT[(size_t)c * R + r] = __float2half(ts[tx][cc]);
    }
}
__global__ void bc_kernel(const float* __restrict__ b_proj,
                          const float* __restrict__ W_x,
                          const float* __restrict__ b_lstm,
                          float* __restrict__ bc) {
    int n = blockIdx.x * blockDim.x + threadIdx.x;
    if (n >= H4) return;
    float s = b_lstm[n];
    for (int k = 0; k < H_SZ; k++) s += b_proj[k] * W_x[(size_t)k * H4 + n];
    bc[n] = s;
}
__global__ void wait_scan_started() {
    long long s0 = clock64();
    while (*((volatile unsigned*)&g_bar) < (unsigned)SCAN_CTAS &&
           clock64() - s0 < 2000000LL)
        __nanosleep(512);
}

// ===================== bf16x3 GEMM (128x128) — Wc only ======================
#define G_SMEM_BYTES (2 * 40960)
__global__ __launch_bounds__(256, 1)
void mma_gemm_bf16(const __nv_bfloat16* __restrict__ Ah, const __nv_bfloat16* __restrict__ Al,
                   const __nv_bfloat16* __restrict__ Bh, const __nv_bfloat16* __restrict__ Bl,
                   __half* __restrict__ C16, int M, int N)
{
    extern __shared__ __align__(16) char smem[];
    const uint32_t sb = smem_u32(smem);
    const int tid = threadIdx.x, lane = tid & 31, wid = tid >> 5;
    const int bm = blockIdx.y * 128, bn = blockIdx.x * 128;
    const int wm = (wid >> 2) * 64, wn = (wid & 3) * 32;

    long a_off[2], b_off[2];
    uint32_t a_s[2], b_s[2], b_sz[2];
#pragma unroll
    for (int q = 0; q < 2; q++) {
        int pos = q * 256 + tid;
        int r = pos >> 2, c8 = (pos & 3) * 8;
        a_off[q] = (long)(bm + r) * H_SZ + c8;
        a_s[q] = (uint32_t)(r * 80 + (pos & 3) * 16);
        int gn = bn + r;
        b_sz[q]  = (gn < N) ? 16u : 0u;
        b_off[q] = (long)((gn < N) ? gn : 0) * H_SZ + c8;
        b_s[q] = a_s[q];
    }

    float acc[4][4][4];
#pragma unroll
    for (int m = 0; m < 4; m++)
#pragma unroll
        for (int j = 0; j < 4; j++)
#pragma unroll
            for (int q = 0; q < 4; q++) acc[m][j][q] = 0.f;

#define GB_LOAD(ck, s) do {                                                   \
    const long ko = (long)(ck) * 32;                                          \
    const uint32_t st = sb + (s) * 40960;                                     \
    _Pragma("unroll")                                                         \
    for (int q = 0; q < 2; q++) {                                             \
        cp16(st + a_s[q],         Ah + a_off[q] + ko, 16u);                   \
        cp16(st + 10240 + a_s[q], Al + a_off[q] + ko, 16u);                   \
        cp16(st + 20480 + b_s[q], Bh + b_off[q] + ko, b_sz[q]);               \
        cp16(st + 30720 + b_s[q], Bl + b_off[q] + ko, b_sz[q]);               \
    }                                                                         \
} while (0)

    GB_LOAD(0, 0); CP_COMMIT();
    GB_LOAD(1, 1); CP_COMMIT();

    for (int ck = 0; ck < 32; ck++) {
        const int s = ck & 1;
        CP_WAIT1();
        __syncthreads();
        const uint32_t sA = sb + s * 40960;
        const uint32_t sB = sA + 20480;
#pragma unroll
        for (int ks = 0; ks < 2; ks++) {
            uint32_t ah[4][4], al[4][4], bh[8], bl[8];
            const int arow = lane & 15;
            const uint32_t ac = (uint32_t)(((lane >> 4) * 8 + ks * 16) * 2);
#pragma unroll
            for (int mf = 0; mf < 4; mf++) {
                uint32_t ad = sA + (uint32_t)((wm + mf * 16 + arow) * 80) + ac;
                ldsm4(ah[mf], ad);
                ldsm4(al[mf], ad + 10240);
            }
            const int brow = (lane & 7) + ((lane >> 4) & 1) * 8;
            const uint32_t bcd = (uint32_t)(((((lane >> 3) & 1) * 8) + ks * 16) * 2);
#pragma unroll
            for (int pf = 0; pf < 2; pf++) {
                uint32_t bd = sB + (uint32_t)((wn + pf * 16 + brow) * 80) + bcd;
                ldsm4(&bh[pf * 4], bd);
                ldsm4(&bl[pf * 4], bd + 10240);
            }
#pragma unroll
            for (int m = 0; m < 4; m++)
#pragma unroll
                for (int j = 0; j < 4; j++) {
                    const int bi = (j >> 1) * 4 + (j & 1) * 2;
                    mma_bf16(acc[m][j], ah[m], bh[bi], bh[bi + 1]);
                    mma_bf16(acc[m][j], al[m], bh[bi], bh[bi + 1]);
                    mma_bf16(acc[m][j], ah[m], bl[bi], bl[bi + 1]);
                }
        }
        __syncthreads();
        if (ck + 2 < 32) GB_LOAD(ck + 2, s);
        CP_COMMIT();
    }

#pragma unroll
    for (int m = 0; m < 4; m++) {
        const int r0 = bm + wm + m * 16 + (lane >> 2);
#pragma unroll
        for (int j = 0; j < 4; j++) {
            const int col = bn + wn + j * 8 + (lane & 3) * 2;
#pragma unroll
            for (int hh = 0; hh < 2; hh++) {
                const int r = r0 + hh * 8;
                if (col < N)     C16[(size_t)r * N + col]     = __float2half(acc[m][j][hh * 2 + 0]);
                if (col + 1 < N) C16[(size_t)r * N + col + 1] = __float2half(acc[m][j][hh * 2 + 1]);
            }
        }
    }
#undef GB_LOAD
}

// ===================== fp16 GEMM (128x256) — pxv only =======================
__global__ __launch_bounds__(256, 1)
void mma_gemm_f16(const __half* __restrict__ Ah,
                  const __half* __restrict__ Bh,
                  const float* __restrict__ bias,
                  float* __restrict__ C, int M, int N)
{
    extern __shared__ __align__(16) char smem[];
    const uint32_t sb = smem_u32(smem);
    const int tid = threadIdx.x, lane = tid & 31, wid = tid >> 5;
    const int bm = blockIdx.y * 128, bn = blockIdx.x * 256;
    const int wm = (wid >> 2) * 64, wn = (wid & 3) * 64;

    long a_off[2];
    uint32_t a_s[2];
#pragma unroll
    for (int q = 0; q < 2; q++) {
        int pos = q * 256 + tid;
        int r = pos >> 2, c8 = (pos & 3) * 8;
        int ar = bm + r; if (ar >= M) ar = M - 1;
        a_off[q] = (long)ar * H_SZ + c8;
        a_s[q] = (uint32_t)(r * 80 + (pos & 3) * 16);
    }
    long b_off[4];
    uint32_t b_s[4], b_sz[4];
#pragma unroll
    for (int q = 0; q < 4; q++) {
        int pos = q * 256 + tid;
        int r = pos >> 2, c8 = (pos & 3) * 8;
        int gn = bn + r;
        b_sz[q]  = (gn < N) ? 16u : 0u;
        b_off[q] = (long)((gn < N) ? gn : 0) * H_SZ + c8;
        b_s[q] = (uint32_t)(r * 80 + (pos & 3) * 16);
    }

    float acc[4][8][4];
#pragma unroll
    for (int m = 0; m < 4; m++)
#pragma unroll
        for (int j = 0; j < 8; j++)
#pragma unroll
            for (int q = 0; q < 4; q++) acc[m][j][q] = 0.f;

#define G2_LOAD(ck, s) do {                                                   \
    const long ko = (long)(ck) * 32;                                          \
    const uint32_t st = sb + (s) * 30720;                                     \
    _Pragma("unroll")                                                         \
    for (int q = 0; q < 2; q++)                                               \
        cp16(st + a_s[q], Ah + a_off[q] + ko, 16u);                           \
    _Pragma("unroll")                                                         \
    for (int q = 0; q < 4; q++)                                               \
        cp16(st + 10240 + b_s[q], Bh + b_off[q] + ko, b_sz[q]);               \
} while (0)

    G2_LOAD(0, 0); CP_COMMIT();
    G2_LOAD(1, 1); CP_COMMIT();

    for (int ck = 0; ck < 32; ck++) {
        const int s = ck & 1;
        CP_WAIT1();
        __syncthreads();
        const uint32_t sA = sb + s * 30720;
        const uint32_t sB = sA + 10240;
#pragma unroll
        for (int ks = 0; ks < 2; ks++) {
            uint32_t ah[4][4], bh[16];
            const int arow = lane & 15;
            const uint32_t ac = (uint32_t)(((lane >> 4) * 8 + ks * 16) * 2);
#pragma unroll
            for (int mf = 0; mf < 4; mf++) {
                uint32_t ad = sA + (uint32_t)((wm + mf * 16 + arow) * 80) + ac;
                ldsm4(ah[mf], ad);
            }
            const int brow = (lane & 7) + ((lane >> 4) & 1) * 8;
            const uint32_t bcd = (uint32_t)(((((lane >> 3) & 1) * 8) + ks * 16) * 2);
#pragma unroll
            for (int pf = 0; pf < 4; pf++) {
                uint32_t bd = sB + (uint32_t)((wn + pf * 16 + brow) * 80) + bcd;
                ldsm4(&bh[pf * 4], bd);
            }
#pragma unroll
            for (int m = 0; m < 4; m++)
#pragma unroll
                for (int j = 0; j < 8; j++) {
                    const int bi = (j >> 1) * 4 + (j & 1) * 2;
                    mma_f16(acc[m][j], ah[m], bh[bi], bh[bi + 1]);
                }
        }
        __syncthreads();
        if (ck + 2 < 32) G2_LOAD(ck + 2, s);
        CP_COMMIT();
    }

#pragma unroll
    for (int m = 0; m < 4; m++) {
        const int r0 = bm + wm + m * 16 + (lane >> 2);
#pragma unroll
        for (int j = 0; j < 8; j++) {
            const int col = bn + wn + j * 8 + (lane & 3) * 2;
#pragma unroll
            for (int hh = 0; hh < 2; hh++) {
                const int r = r0 + hh * 8;
                if (col < N)     C[(size_t)r * N + col]     = acc[m][j][hh * 2 + 0] + bias[col];
                if (col + 1 < N) C[(size_t)r * N + col + 1] = acc[m][j][hh * 2 + 1] + bias[col + 1];
            }
        }
    }
#undef G2_LOAD
}

// ===================== slim fp16 GEMM (128x128) — out overlap/fixup =========
// ~110 regs, 41 KB smem -> co-resides with the persistent scan on every SM.
// MODE 1: overlap (wait scan progress, mark done, give up on stall).
// MODE 2: fixup (skip done tiles).
#define GO_SMEM (2 * 20480)
template <int MODE>
__global__ __launch_bounds__(256, 1)
void mma_out128(const __half* __restrict__ Ah,
                const __half* __restrict__ Bh,
                const float* __restrict__ bias,
                float* __restrict__ C, int M, int N)
{
    extern __shared__ __align__(16) char smem[];
    const uint32_t sb = smem_u32(smem);
    const int tid = threadIdx.x, lane = tid & 31, wid = tid >> 5;

    const int tileId = blockIdx.y * gridDim.x + blockIdx.x;
    if (MODE == 2) {
        if (g_done[tileId]) return;
    }
    if (MODE == 1) {
        __shared__ int s_go;
        if (tid == 0) {
            const int k = blockIdx.y >> 3;                  // 1024-row M-chunk
            const unsigned needed = 2048u * (unsigned)(k + 1);
            volatile unsigned* prog = (volatile unsigned*)&g_bar;
            unsigned cur = *prog;
            long long lastChg = clock64();
            int go = 1;
            while (cur < needed) {
                __nanosleep(256);
                unsigned now = *prog;
                if (now != cur) { cur = now; lastChg = clock64(); }
                else if (clock64() - lastChg > 150000LL) { go = 0; break; }
            }
            s_go = go;
        }
        __syncthreads();
        if (!s_go) return;
        __threadfence();
    }

    const int bm = blockIdx.y * 128, bn = blockIdx.x * 128;
    const int wm = (wid >> 2) * 64, wn = (wid & 3) * 32;

    long a_off[2], b_off[2];
    uint32_t a_s[2], b_sz[2];
#pragma unroll
    for (int q = 0; q < 2; q++) {
        int pos = q * 256 + tid;
        int r = pos >> 2, c8 = (pos & 3) * 8;
        int ar = bm + r; if (ar >= M) ar = M - 1;
        a_off[q] = (long)ar * H_SZ + c8;
        a_s[q] = (uint32_t)(r * 80 + (pos & 3) * 16);
        int gn = bn + r;
        b_sz[q]  = (gn < N) ? 16u : 0u;
        b_off[q] = (long)((gn < N) ? gn : 0) * H_SZ + c8;
    }

    float acc[4][4][4];
#pragma unroll
    for (int m = 0; m < 4; m++)
#pragma unroll
        for (int j = 0; j < 4; j++)
#pragma unroll
            for (int q = 0; q < 4; q++) acc[m][j][q] = 0.f;

#define GO_LOAD(ck, s) do {                                                   \
    const long ko = (long)(ck) * 32;                                          \
    const uint32_t st = sb + (s) * 20480;                                     \
    _Pragma("unroll")                                                         \
    for (int q = 0; q < 2; q++) {                                             \
        cp16(st + a_s[q],         Ah + a_off[q] + ko, 16u);                   \
        cp16(st + 10240 + a_s[q], Bh + b_off[q] + ko, b_sz[q]);               \
    }                                                                         \
} while (0)

    GO_LOAD(0, 0); CP_COMMIT();
    GO_LOAD(1, 1); CP_COMMIT();

    for (int ck = 0; ck < 32; ck++) {
        const int s = ck & 1;
        CP_WAIT1();
        __syncthreads();
        const uint32_t sA = sb + s * 20480;
        const uint32_t sB = sA + 10240;
#pragma unroll
        for (int ks = 0; ks < 2; ks++) {
            uint32_t ah[4][4], bh[8];
            const int arow = lane & 15;
            const uint32_t ac = (uint32_t)(((lane >> 4) * 8 + ks * 16) * 2);
#pragma unroll
            for (int mf = 0; mf < 4; mf++) {
                uint32_t ad = sA + (uint32_t)((wm + mf * 16 + arow) * 80) + ac;
                ldsm4(ah[mf], ad);
            }
            const int brow = (lane & 7) + ((lane >> 4) & 1) * 8;
            const uint32_t bcd = (uint32_t)(((((lane >> 3) & 1) * 8) + ks * 16) * 2);
#pragma unroll
            for (int pf = 0; pf < 2; pf++) {
                uint32_t bd = sB + (uint32_t)((wn + pf * 16 + brow) * 80) + bcd;
                ldsm4(&bh[pf * 4], bd);
            }
#pragma unroll
            for (int m = 0; m < 4; m++)
#pragma unroll
                for (int j = 0; j < 4; j++) {
                    const int bi = (j >> 1) * 4 + (j & 1) * 2;
                    mma_f16(acc[m][j], ah[m], bh[bi], bh[bi + 1]);
                }
        }
        __syncthreads();
        if (ck + 2 < 32) GO_LOAD(ck + 2, s);
        CP_COMMIT();
    }

#pragma unroll
    for (int m = 0; m < 4; m++) {
        const int r0 = bm + wm + m * 16 + (lane >> 2);
#pragma unroll
        for (int j = 0; j < 4; j++) {
            const int col = bn + wn + j * 8 + (lane & 3) * 2;
#pragma unroll
            for (int hh = 0; hh < 2; hh++) {
                const int r = r0 + hh * 8;
                if (col < N)     C[(size_t)r * N + col]     = acc[m][j][hh * 2 + 0] + bias[col];
                if (col + 1 < N) C[(size_t)r * N + col + 1] = acc[m][j][hh * 2 + 1] + bias[col + 1];
            }
        }
    }
    if (MODE == 1) {
        __syncthreads();
        if (tid == 0) g_done[tileId] = 1u;
    }
#undef GO_LOAD
}

// ===================== persistent LSTM scan (8 warps, K-split) ==============
#define A_BYTES   (32 * 2560)
#define SB_STG    5120
#define RING_BYTES (4 * SB_STG)
#define SCAN_SMEM (A_BYTES + 2 * RING_BYTES)   // 122880 B

__global__ __launch_bounds__(256, 1)
void lstm_scan_persistent(const __half* __restrict__ WhT16,
                          const float* __restrict__ pxv,   // [V, 4H]
                          const int* __restrict__ xidx,    // [T, B]
                          const float* __restrict__ c_in,
                          __half* __restrict__ res,        // (T+1) slabs [B,H]
                          float* __restrict__ hf, float* __restrict__ cf)
{
    extern __shared__ __align__(16) char smem[];
    const uint32_t sb = smem_u32(smem);
    const int tid = threadIdx.x, lane = tid & 31, wid = tid >> 5;
    const int half = wid >> 2;
    const int wq = wid & 3;
    const int u0 = blockIdx.x * 8;
    const int wm = (wq >> 1) * 16, wn = (wq & 1) * 32;

    for (int idx = tid; idx < 4096; idx += 256) {
        int ck = idx >> 7, pos = idx & 127;
        int r = pos >> 2, seg = pos & 3;
        long grow = (long)(r >> 3) * H_SZ + u0 + (r & 7);
        const __half* src = WhT16 + grow * H_SZ + ck * 32 + seg * 8;
        cp16(sb + (uint32_t)(ck * 2560 + r * 80 + seg * 16), src, 16u);
    }
    CP_COMMIT();

    const int u = tid & 7;
    const int b0 = (tid >> 3) * 2;
    const int gu = u0 + u;
    float creg[2];
#pragma unroll
    for (int jj = 0; jj < 2; jj++) creg[jj] = c_in[(b0 + jj) * H_SZ + gu];

    const int htid = tid & 127;
    uint32_t b_s[2];
    long b_row[2];
#pragma unroll
    for (int q = 0; q < 2; q++) {
        int pos = q * 128 + htid;
        int r = pos >> 2, c8 = (pos & 3) * 8;
        b_row[q] = (long)r * H_SZ + c8;
        b_s[q] = (uint32_t)(r * 80 + (pos & 3) * 16);
    }
    const uint32_t ringb = sb + A_BYTES + (uint32_t)half * RING_BYTES;
    float* Gs0 = (float*)(smem + A_BYTES);
    float* Gs1 = (float*)(smem + A_BYTES + RING_BYTES);
    float* GsH = half ? Gs1 : Gs0;

    CP_WAIT0();
    __syncthreads();

#define SB_LOAD(hhp, ck, s) do {                                              \
    const long ko = (long)(ck) * 32;                                          \
    const uint32_t st = ringb + (s) * SB_STG;                                 \
    _Pragma("unroll")                                                         \
    for (int q = 0; q < 2; q++)                                               \
        cp16(st + b_s[q], (hhp) + b_row[q] + ko, 16u);                        \
} while (0)

    const int ck0 = half * 16;

    for (int t = 0; t < T_STEPS; t++) {
        const __half* hh = res + (size_t)t * BH;
        __half*       oh = res + (size_t)(t + 1) * BH;

        float pr[2][4];
#pragma unroll
        for (int jj = 0; jj < 2; jj++) {
            const int row = xidx[t * B_SZ + b0 + jj];
            const float* pxb = pxv + (size_t)row * H4;
            pr[jj][0] = pxb[gu];
            pr[jj][1] = pxb[1024 + gu];
            pr[jj][2] = pxb[2048 + gu];
            pr[jj][3] = pxb[3072 + gu];
        }

        float acc[4][4];
#pragma unroll
        for (int j = 0; j < 4; j++)
#pragma unroll
            for (int q = 0; q < 4; q++) acc[j][q] = 0.f;

        SB_LOAD(hh, ck0 + 0, 0); CP_COMMIT();
        SB_LOAD(hh, ck0 + 1, 1); CP_COMMIT();
        SB_LOAD(hh, ck0 + 2, 2); CP_COMMIT();

        for (int i = 0; i < 16; i++) {
            const int s = i & 3;
            CP_WAIT2();
            BAR_SYNC(1 + half, 128);
            const uint32_t sA = sb + (uint32_t)((ck0 + i) * 2560);
            const uint32_t sB = ringb + s * SB_STG;
#pragma unroll
            for (int ks = 0; ks < 2; ks++) {
                uint32_t ah[4], bh[8];
                const uint32_t ac = (uint32_t)(((lane >> 4) * 8 + ks * 16) * 2);
                ldsm4(ah, sA + (uint32_t)((wm + (lane & 15)) * 80) + ac);
                const int brow = (lane & 7) + ((lane >> 4) & 1) * 8;
                const uint32_t bcd = (uint32_t)(((((lane >> 3) & 1) * 8) + ks * 16) * 2);
#pragma unroll
                for (int pf = 0; pf < 2; pf++) {
                    uint32_t bd = sB + (uint32_t)((wn + pf * 16 + brow) * 80) + bcd;
                    ldsm4(&bh[pf * 4], bd);
                }
#pragma unroll
                for (int j = 0; j < 4; j++) {
                    const int bi = (j >> 1) * 4 + (j & 1) * 2;
                    mma_f16(acc[j], ah, bh[bi], bh[bi + 1]);
                }
            }
            if (i + 3 < 16) { SB_LOAD(hh, ck0 + i + 3, (i + 3) & 3); }
            CP_COMMIT();
        }

        BAR_SYNC(1 + half, 128);
        {
            const int row = wm + (lane >> 2);
#pragma unroll
            for (int j = 0; j < 4; j++) {
                const int col = wn + j * 8 + (lane & 3) * 2;
                GsH[row * 65 + col]           = acc[j][0];
                GsH[row * 65 + col + 1]       = acc[j][1];
                GsH[(row + 8) * 65 + col]     = acc[j][2];
                GsH[(row + 8) * 65 + col + 1] = acc[j][3];
            }
        }
        __syncthreads();

#pragma unroll
        for (int jj = 0; jj < 2; jj++) {
            const int b = b0 + jj;
            float gi = Gs0[(0 * 8 + u) * 65 + b] + Gs1[(0 * 8 + u) * 65 + b] + pr[jj][0];
            float gf = Gs0[(1 * 8 + u) * 65 + b] + Gs1[(1 * 8 + u) * 65 + b] + pr[jj][1];
            float gg = Gs0[(2 * 8 + u) * 65 + b] + Gs1[(2 * 8 + u) * 65 + b] + pr[jj][2];
            float go = Gs0[(3 * 8 + u) * 65 + b] + Gs1[(3 * 8 + u) * 65 + b] + pr[jj][3];
            float si = fsig(gi);
            float sf = fsig(gf);
            float so = fsig(go);
            float tg = ftanh(gg);
            float cn = sf * creg[jj] + si * tg;
            float hn = so * ftanh(cn);
            creg[jj] = cn;
            const int ci = b * H_SZ + gu;
            oh[ci] = __float2half(hn);
            if (t == T_STEPS - 1) { hf[ci] = hn; cf[ci] = cn; }
        }

        __threadfence();
        __syncthreads();
        if (tid == 0) {
            atomicAdd(&g_bar, 1u);
            if (t < T_STEPS - 1) {
                const unsigned target = (unsigned)SCAN_CTAS * (unsigned)(t + 1);
                while (atomicAdd(&g_bar, 0u) < target) { }
            }
        }
        __syncthreads();
        __threadfence();
    }
#undef SB_LOAD
}

// ===================== launch ================================================
extern "C" void kernel_launch(void* const* d_in, const int* in_sizes, int n_in,
                              void* d_out, int out_size)
{
    const int*   x      = (const int*)  d_in[0];
    const float* h      = (const float*)d_in[1];
    const float* c      = (const float*)d_in[2];
    const float* emb    = (const float*)d_in[3];
    const float* W_proj = (const float*)d_in[4];
    const float* b_proj = (const float*)d_in[5];
    const float* W_x    = (const float*)d_in[6];
    const float* W_h    = (const float*)d_in[7];
    const float* b_lstm = (const float*)d_in[8];
    const float* W_out  = (const float*)d_in[9];
    const float* b_out  = (const float*)d_in[10];
    float* out = (float*)d_out;

    float *pxv, *bc;
    unsigned int *bar, *done;
    __nv_bfloat16 *wxth, *wxtl, *wph, *wpl;
    __half *r16h, *e16h, *wht16, *wot16, *wct16;
    cudaGetSymbolAddress((void**)&pxv,   g_px);
    cudaGetSymbolAddress((void**)&bc,    g_bc);
    cudaGetSymbolAddress((void**)&bar,   g_bar);
    cudaGetSymbolAddress((void**)&done,  g_done);
    cudaGetSymbolAddress((void**)&r16h,  g_res16h);
    cudaGetSymbolAddress((void**)&e16h,  g_emb16h);
    cudaGetSymbolAddress((void**)&wxth,  g_WxT_hi);
    cudaGetSymbolAddress((void**)&wxtl,  g_WxT_lo);
    cudaGetSymbolAddress((void**)&wht16, g_WhT16);
    cudaGetSymbolAddress((void**)&wot16, g_WoT16);
    cudaGetSymbolAddress((void**)&wph,   g_Wp_hi);
    cudaGetSymbolAddress((void**)&wpl,   g_Wp_lo);
    cudaGetSymbolAddress((void**)&wct16, g_WcT16);

    cudaFuncSetAttribute(mma_gemm_bf16,
                         cudaFuncAttributeMaxDynamicSharedMemorySize, G_SMEM_BYTES);
    cudaFuncSetAttribute(mma_gemm_f16,
                         cudaFuncAttributeMaxDynamicSharedMemorySize, 2 * 30720);
    cudaFuncSetAttribute(mma_out128<1>,
                         cudaFuncAttributeMaxDynamicSharedMemorySize, GO_SMEM);
    cudaFuncSetAttribute(mma_out128<2>,
                         cudaFuncAttributeMaxDynamicSharedMemorySize, GO_SMEM);
    cudaFuncSetAttribute(lstm_scan_persistent,
                         cudaFuncAttributeMaxDynamicSharedMemorySize, SCAN_SMEM);

    // ---------- prepass (stream 0) ----------
    cudaMemsetAsync(bar, 0, sizeof(unsigned int), 0);
    cudaMemsetAsync(done, 0, OT_X * OT_Y * sizeof(unsigned int), 0);
    split_kernel<<<512, 256>>>(W_proj, wph, wpl, (long)H_SZ * H_SZ);
    conv16_kernel<<<2048, 256>>>(emb, e16h, (long)O_SZ * H_SZ);
    conv16_kernel<<<64, 256>>>(h, r16h, (long)BH);   // slab 0 = h_{-1}
    transpose_split_kernel<<<dim3(H4 / 32, H_SZ / 32), 256>>>(W_x, wxth, wxtl, H_SZ, H4);
    transpose16_kernel<<<dim3(H4 / 32, H_SZ / 32), 256>>>(W_h, wht16, H_SZ, H4);
    transpose16_kernel<<<dim3((O_SZ + 31) / 32, H_SZ / 32), 256>>>(W_out, wot16, H_SZ, O_SZ);
    bc_kernel<<<(H4 + 255) / 256, 256>>>(b_proj, W_x, b_lstm, bc);

    // ---------- Wc, then pxv (stream 0) ----------
    mma_gemm_bf16<<<dim3(H_SZ / 128, H4 / 128), 256, G_SMEM_BYTES>>>(
        wxth, wxtl, wph, wpl, wct16, H4, H_SZ);
    mma_gemm_f16<<<dim3(H4 / 256, (V_SZ + 127) / 128), 256, 2 * 30720>>>(
        e16h, wct16, bc, pxv, V_SZ, H4);
    cudaEventRecord(g_evPx, 0);

    // ---------- persistent scan (stream 0) ----------
    float* hf_out = out + (size_t)TB * O_SZ;
    float* cf_out = hf_out + BH;
    lstm_scan_persistent<<<SCAN_CTAS, 256, SCAN_SMEM>>>(
        wht16, pxv, x, c, r16h, hf_out, cf_out);

    // ---------- overlapped slim out GEMM on s1 ----------
    cudaStreamWaitEvent(g_s1, g_evPx, 0);
    wait_scan_started<<<1, 1, 0, g_s1>>>();
    mma_out128<1><<<dim3(OT_X, OT_Y), 256, GO_SMEM, g_s1>>>(
        r16h + BH, wot16, b_out, out, TB, O_SZ);
    cudaEventRecord(g_evOv, g_s1);

    // ---------- fixup pass (stream 0, after scan AND overlap) ----------
    cudaStreamWaitEvent(0, g_evOv, 0);
    mma_out128<2><<<dim3(OT_X, OT_Y), 256, GO_SMEM>>>(
        r16h + BH, wot16, b_out, out, TB, O_SZ);
}